// round 6
// baseline (speedup 1.0000x reference)
#include <cuda_runtime.h>
#include <math.h>
#include <stdint.h>

#define D_MODEL   256
#define N_LAYERS  6
#define N_HEADS   8
#define D_FF      1024
#define HEAD_DIM  32
#define BATCH     4
#define SEQ       2048
#define NTOK      (BATCH * SEQ)   // 8192

// ---------------------------------------------------------------------------
// Scratch
// ---------------------------------------------------------------------------
__device__ float g_normed[NTOK * D_MODEL];
__device__ float g_q[NTOK * D_MODEL];
__device__ float g_k[NTOK * D_MODEL];
__device__ float g_v[NTOK * D_MODEL];
__device__ float g_attn[NTOK * D_MODEL];
__device__ float g_ffh[NTOK * D_FF];

// ---------------------------------------------------------------------------
// Helpers
// ---------------------------------------------------------------------------
__device__ __forceinline__ uint32_t smem_u32(const void* p) {
    return (uint32_t)__cvta_generic_to_shared(p);
}
#define CPA16(dst_u32, src_ptr) \
    asm volatile("cp.async.cg.shared.global [%0], [%1], 16;\n" :: "r"(dst_u32), "l"(src_ptr))
#define CPA_COMMIT() asm volatile("cp.async.commit_group;\n" ::)
#define CPA_WAIT2()  asm volatile("cp.async.wait_group 2;\n" ::)
#define CPA_WAIT1()  asm volatile("cp.async.wait_group 1;\n" ::)
#define CPA_WAIT0()  asm volatile("cp.async.wait_group 0;\n" ::)

__device__ __forceinline__ void mma_tf32(float* c, const uint32_t* a, const uint32_t* b) {
    asm volatile(
        "mma.sync.aligned.m16n8k8.row.col.f32.tf32.tf32.f32 "
        "{%0,%1,%2,%3},{%4,%5,%6,%7},{%8,%9},{%0,%1,%2,%3};\n"
        : "+f"(c[0]), "+f"(c[1]), "+f"(c[2]), "+f"(c[3])
        : "r"(a[0]), "r"(a[1]), "r"(a[2]), "r"(a[3]),
          "r"(b[0]), "r"(b[1]));
}

__device__ __forceinline__ void ldsm4(uint32_t* r, uint32_t byte_addr) {
    asm volatile("ldmatrix.sync.aligned.m8n8.x4.shared.b16 {%0,%1,%2,%3}, [%4];\n"
        : "=r"(r[0]), "=r"(r[1]), "=r"(r[2]), "=r"(r[3]) : "r"(byte_addr));
}

__device__ __forceinline__ float ex2(float x) {
    float y;
    asm("ex2.approx.f32 %0, %1;" : "=f"(y) : "f"(x));
    return y;
}

// ---------------------------------------------------------------------------
// LayerNorm
// ---------------------------------------------------------------------------
__global__ void __launch_bounds__(256) ln_kernel(
    const float* __restrict__ X, const float* __restrict__ S,
    const float* __restrict__ Bb, float* __restrict__ Y)
{
    const int row = blockIdx.x;
    const int tid = threadIdx.x;
    const float v = X[row * D_MODEL + tid];

    __shared__ float red[16];
    float s1 = v, s2 = v * v;
    #pragma unroll
    for (int off = 16; off > 0; off >>= 1) {
        s1 += __shfl_xor_sync(0xffffffffu, s1, off);
        s2 += __shfl_xor_sync(0xffffffffu, s2, off);
    }
    const int w = tid >> 5;
    if ((tid & 31) == 0) { red[w] = s1; red[8 + w] = s2; }
    __syncthreads();
    float sum = 0.f, sq = 0.f;
    #pragma unroll
    for (int i = 0; i < 8; i++) { sum += red[i]; sq += red[8 + i]; }
    const float mu  = sum * (1.0f / D_MODEL);
    const float var = sq * (1.0f / D_MODEL) - mu * mu;
    const float inv = rsqrtf(var + 1e-5f);
    Y[row * D_MODEL + tid] = (v - mu) * inv * S[tid] + Bb[tid];
}

// ---------------------------------------------------------------------------
// tf32 GEMM: block 64x64, BK=32, 128 threads (4 warps as 2m x 2n, 32x32/warp)
// A-frags via ldmatrix.x4, W-frags scalar LDS, 3-stage cp.async pipeline.
// ---------------------------------------------------------------------------
#define GEMM_SMEM_BYTES (3 * (64 * 36 + 32 * 72) * 4)

template <bool GELU, bool RES>
__device__ __forceinline__ void gemm_body(
    const float* __restrict__ A, const float* __restrict__ W,
    const float* __restrict__ bias, float* __restrict__ C,
    int K, int M)
{
    extern __shared__ __align__(16) uint32_t dynsmem[];
    uint32_t* As = dynsmem;                 // [3][64*36]
    uint32_t* Ws = dynsmem + 3 * 64 * 36;   // [3][32*72]

    const int tid  = threadIdx.x;
    const int lane = tid & 31;
    const int wid  = tid >> 5;
    const int warp_m = wid >> 1;
    const int warp_n = wid & 1;
    const int r0   = lane >> 2;
    const int quad = lane & 3;
    const int row0 = blockIdx.y * 64;
    const int col0 = blockIdx.x * 64;

    const int lm_row = lane & 15;
    const int lm_col = (lane >> 4) << 2;

    float acc[2][4][4] = {};

    auto load_stage = [&](int k0, int s) {
        const float* Ab = A + (size_t)row0 * K + k0;
        uint32_t* Asb = As + s * (64 * 36);
        #pragma unroll
        for (int i = 0; i < 4; i++) {
            int r = (tid >> 3) + i * 16;
            int c4 = tid & 7;
            CPA16(smem_u32(&Asb[r * 36 + c4 * 4]), Ab + (size_t)r * K + c4 * 4);
        }
        const float* Wb = W + (size_t)k0 * M + col0;
        uint32_t* Wsb = Ws + s * (32 * 72);
        #pragma unroll
        for (int i = 0; i < 4; i++) {
            int r = (tid >> 4) + i * 8;
            int c4 = tid & 15;
            CPA16(smem_u32(&Wsb[r * 72 + c4 * 4]), Wb + (size_t)r * M + c4 * 4);
        }
        CPA_COMMIT();
    };

    const int nk = K >> 5;
    load_stage(0, 0);
    load_stage(32, 1);

    for (int it = 0; it < nk; ++it) {
        const int s = it % 3;
        if (it + 2 < nk)      { load_stage((it + 2) * 32, (it + 2) % 3); CPA_WAIT2(); }
        else if (it + 1 < nk) { CPA_WAIT1(); }
        else                  { CPA_WAIT0(); }
        __syncthreads();

        const uint32_t* Asb = As + s * (64 * 36);
        const uint32_t* Wsb = Ws + s * (32 * 72);

        #pragma unroll
        for (int ks = 0; ks < 4; ks++) {
            const int kk = ks * 8;
            uint32_t a[2][4], b[4][2];
            #pragma unroll
            for (int mi = 0; mi < 2; mi++) {
                const int rb = warp_m * 32 + mi * 16;
                ldsm4(a[mi], smem_u32(&Asb[(rb + lm_row) * 36 + kk + lm_col]));
            }
            #pragma unroll
            for (int ni = 0; ni < 4; ni++) {
                const int cb = warp_n * 32 + ni * 8 + r0;
                b[ni][0] = Wsb[(kk + quad) * 72 + cb];
                b[ni][1] = Wsb[(kk + 4 + quad) * 72 + cb];
            }
            #pragma unroll
            for (int mi = 0; mi < 2; mi++)
                #pragma unroll
                for (int ni = 0; ni < 4; ni++)
                    mma_tf32(acc[mi][ni], a[mi], b[ni]);
        }
        __syncthreads();
    }

    #pragma unroll
    for (int mi = 0; mi < 2; mi++) {
        #pragma unroll
        for (int ni = 0; ni < 4; ni++) {
            const int r = row0 + warp_m * 32 + mi * 16 + r0;
            const int c = col0 + warp_n * 32 + ni * 8 + 2 * quad;
            const float bx = bias[c], by = bias[c + 1];
            float v0 = acc[mi][ni][0] + bx;
            float v1 = acc[mi][ni][1] + by;
            float v2 = acc[mi][ni][2] + bx;
            float v3 = acc[mi][ni][3] + by;
            if (GELU) {
                v0 = 0.5f * v0 * (1.0f + erff(v0 * 0.70710678118654752f));
                v1 = 0.5f * v1 * (1.0f + erff(v1 * 0.70710678118654752f));
                v2 = 0.5f * v2 * (1.0f + erff(v2 * 0.70710678118654752f));
                v3 = 0.5f * v3 * (1.0f + erff(v3 * 0.70710678118654752f));
            }
            if (RES) {
                float2 e0 = *reinterpret_cast<const float2*>(&C[(size_t)r * M + c]);
                float2 e1 = *reinterpret_cast<const float2*>(&C[(size_t)(r + 8) * M + c]);
                v0 += e0.x; v1 += e0.y; v2 += e1.x; v3 += e1.y;
            }
            *reinterpret_cast<float2*>(&C[(size_t)r * M + c])       = make_float2(v0, v1);
            *reinterpret_cast<float2*>(&C[(size_t)(r + 8) * M + c]) = make_float2(v2, v3);
        }
    }
}

template <bool GELU, bool RES>
__global__ void __launch_bounds__(128) gemm_kernel(
    const float* __restrict__ A, const float* __restrict__ W,
    const float* __restrict__ bias, float* __restrict__ C, int K, int M)
{
    gemm_body<GELU, RES>(A, W, bias, C, K, M);
}

__global__ void __launch_bounds__(128) qkv_kernel(
    const float* __restrict__ A,
    const float* __restrict__ wq, const float* __restrict__ wk, const float* __restrict__ wv,
    const float* __restrict__ bq, const float* __restrict__ bk, const float* __restrict__ bv,
    float* __restrict__ q, float* __restrict__ k, float* __restrict__ v)
{
    const float* W; const float* B; float* C;
    if (blockIdx.z == 0)      { W = wq; B = bq; C = q; }
    else if (blockIdx.z == 1) { W = wk; B = bk; C = k; }
    else                      { W = wv; B = bv; C = v; }
    gemm_body<false, false>(A, W, B, C, D_MODEL, D_MODEL);
}

// ---------------------------------------------------------------------------
// Flash attention: CTA = 256 queries, 8 warps (warp = 32 queries, mi=2).
// K/V tiles of 64 keys shared by all 8 warps, 3-stage cp.async pipeline.
// Softmax in log2 domain. Q frags in regs; K/P frags via ldmatrix; V scalar.
// smem: Ps[256*68] (aliased as Q staging at start) + 3*(Ks[64*36]+Vs[64*40])
//     = (17408 + 14592) * 4 = 128000 B -> 1 CTA/SM, 8 warps.
// ---------------------------------------------------------------------------
#define ATTN_SMEM_BYTES ((256 * 68 + 3 * (64 * 36 + 64 * 40)) * 4)

__global__ void __launch_bounds__(256) attn_kernel(
    const float* __restrict__ Q, const float* __restrict__ K,
    const float* __restrict__ V, float* __restrict__ O)
{
    extern __shared__ __align__(16) uint32_t dyn[];
    uint32_t* Ps = dyn;                      // 256*68 (Q staged here at pitch 36 first)
    uint32_t* Ks = Ps + 256 * 68;            // [3][64*36]
    uint32_t* Vs = Ks + 3 * 64 * 36;         // [3][64*40]
    uint32_t* Qstage = Ps;                   // alias, pitch 36

    const int tid  = threadIdx.x;
    const int lane = tid & 31;
    const int w    = tid >> 5;               // warp 0..7
    const int r0   = lane >> 2;
    const int quad = lane & 3;
    const int q0   = blockIdx.x * 256;
    const int h    = blockIdx.y;
    const int b    = blockIdx.z;
    const float scale2 = 0.17677669529663687f * 1.4426950408889634f;  // /sqrt(32)*log2(e)
    const int base = (b * SEQ) * D_MODEL + h * HEAD_DIM;

    const int lm_row = lane & 15;
    const int lm_col = (lane >> 4) << 2;
    const int lmb_row = (lane & 7) + ((lane >> 4) << 3);
    const int lmb_col = ((lane >> 3) & 1) << 2;

    auto load_kv = [&](int kt, int s) {
        uint32_t* Ksb = Ks + s * (64 * 36);
        uint32_t* Vsb = Vs + s * (64 * 40);
        #pragma unroll
        for (int i = 0; i < 2; i++) {
            const int e = tid + i * 256;      // 0..511
            const int r = e >> 3, c4 = e & 7;
            CPA16(smem_u32(&Ksb[r * 36 + c4 * 4]), &K[base + (kt + r) * D_MODEL + c4 * 4]);
            CPA16(smem_u32(&Vsb[r * 40 + c4 * 4]), &V[base + (kt + r) * D_MODEL + c4 * 4]);
        }
        CPA_COMMIT();
    };

    load_kv(0, 0);
    load_kv(64, 1);

    // Stage Q (scaled to log2 domain) at pitch 36 in the Ps region
    #pragma unroll
    for (int i = 0; i < 8; i++) {
        int e = tid + i * 256;                // 0..2047 float4 chunks
        int r = e >> 3, c4 = e & 7;
        float4 v = *reinterpret_cast<const float4*>(&Q[base + (q0 + r) * D_MODEL + c4 * 4]);
        uint4 u = make_uint4(__float_as_uint(v.x * scale2), __float_as_uint(v.y * scale2),
                             __float_as_uint(v.z * scale2), __float_as_uint(v.w * scale2));
        *reinterpret_cast<uint4*>(&Qstage[r * 36 + c4 * 4]) = u;
    }
    __syncthreads();

    uint32_t qf[2][4][4];
    #pragma unroll
    for (int mi = 0; mi < 2; mi++) {
        const int rb = w * 32 + mi * 16;
        #pragma unroll
        for (int ks = 0; ks < 4; ks++)
            ldsm4(qf[mi][ks], smem_u32(&Qstage[(rb + lm_row) * 36 + ks * 8 + lm_col]));
    }
    __syncthreads();   // all warps have Q in regs; Ps region free for P

    float m[2][2], l[2][2], o[2][4][4] = {};
    #pragma unroll
    for (int mi = 0; mi < 2; mi++) { m[mi][0] = m[mi][1] = -1e30f; l[mi][0] = l[mi][1] = 0.f; }

    const int NIT = SEQ / 64;
    for (int it = 0; it < NIT; ++it) {
        const int s = it % 3;
        if (it + 2 < NIT)      { load_kv((it + 2) * 64, (it + 2) % 3); CPA_WAIT2(); }
        else if (it + 1 < NIT) { CPA_WAIT1(); }
        else                   { CPA_WAIT0(); }
        __syncthreads();

        const uint32_t* Ksb = Ks + s * (64 * 36);
        const uint32_t* Vsb = Vs + s * (64 * 40);

        // S = Q K^T
        float sc[2][8][4] = {};
        #pragma unroll
        for (int ks = 0; ks < 4; ks++) {
            const int kk = ks * 8;
            uint32_t bfr[4][4];
            #pragma unroll
            for (int nq = 0; nq < 4; nq++)
                ldsm4(bfr[nq], smem_u32(&Ksb[(nq * 16 + lmb_row) * 36 + kk + lmb_col]));
            #pragma unroll
            for (int mi = 0; mi < 2; mi++) {
                #pragma unroll
                for (int nq = 0; nq < 4; nq++) {
                    mma_tf32(sc[mi][2 * nq],     qf[mi][ks], &bfr[nq][0]);
                    mma_tf32(sc[mi][2 * nq + 1], qf[mi][ks], &bfr[nq][2]);
                }
            }
        }

        // Online softmax (base-2), P -> smem
        #pragma unroll
        for (int mi = 0; mi < 2; mi++) {
            const int rb = w * 32 + mi * 16 + r0;
            float mt0 = -1e30f, mt1 = -1e30f;
            #pragma unroll
            for (int ni = 0; ni < 8; ni++) {
                mt0 = fmaxf(mt0, fmaxf(sc[mi][ni][0], sc[mi][ni][1]));
                mt1 = fmaxf(mt1, fmaxf(sc[mi][ni][2], sc[mi][ni][3]));
            }
            #pragma unroll
            for (int off = 1; off < 4; off <<= 1) {
                mt0 = fmaxf(mt0, __shfl_xor_sync(0xffffffffu, mt0, off));
                mt1 = fmaxf(mt1, __shfl_xor_sync(0xffffffffu, mt1, off));
            }
            const float mn0 = fmaxf(m[mi][0], mt0);
            const float mn1 = fmaxf(m[mi][1], mt1);
            const float alpha0 = ex2(m[mi][0] - mn0);
            const float alpha1 = ex2(m[mi][1] - mn1);
            m[mi][0] = mn0; m[mi][1] = mn1;

            float rs0 = 0.f, rs1 = 0.f;
            #pragma unroll
            for (int ni = 0; ni < 8; ni++) {
                const float p00 = ex2(sc[mi][ni][0] - mn0);
                const float p01 = ex2(sc[mi][ni][1] - mn0);
                const float p10 = ex2(sc[mi][ni][2] - mn1);
                const float p11 = ex2(sc[mi][ni][3] - mn1);
                rs0 += p00 + p01;
                rs1 += p10 + p11;
                const int col = ni * 8 + 2 * quad;
                *reinterpret_cast<float2*>(&Ps[rb * 68 + col])       = make_float2(p00, p01);
                *reinterpret_cast<float2*>(&Ps[(rb + 8) * 68 + col]) = make_float2(p10, p11);
            }
            #pragma unroll
            for (int off = 1; off < 4; off <<= 1) {
                rs0 += __shfl_xor_sync(0xffffffffu, rs0, off);
                rs1 += __shfl_xor_sync(0xffffffffu, rs1, off);
            }
            l[mi][0] = l[mi][0] * alpha0 + rs0;
            l[mi][1] = l[mi][1] * alpha1 + rs1;
            #pragma unroll
            for (int ni = 0; ni < 4; ni++) {
                o[mi][ni][0] *= alpha0; o[mi][ni][1] *= alpha0;
                o[mi][ni][2] *= alpha1; o[mi][ni][3] *= alpha1;
            }
        }
        __syncwarp();   // Ps rows are warp-private: order write -> ldmatrix read

        // O += P @ V
        #pragma unroll
        for (int ks = 0; ks < 8; ks++) {
            const int kk = ks * 8;
            uint32_t a[2][4];
            #pragma unroll
            for (int mi = 0; mi < 2; mi++) {
                const int rb = w * 32 + mi * 16;
                ldsm4(a[mi], smem_u32(&Ps[(rb + lm_row) * 68 + kk + lm_col]));
            }
            #pragma unroll
            for (int ni = 0; ni < 4; ni++) {
                uint32_t bb[2];
                const int nb = ni * 8 + r0;
                bb[0] = Vsb[(kk + quad) * 40 + nb];
                bb[1] = Vsb[(kk + 4 + quad) * 40 + nb];
                #pragma unroll
                for (int mi = 0; mi < 2; mi++)
                    mma_tf32(o[mi][ni], a[mi], bb);
            }
        }
        __syncthreads();   // stage s fully consumed before it gets overwritten
    }

    #pragma unroll
    for (int mi = 0; mi < 2; mi++) {
        const float inv0 = 1.0f / l[mi][0];
        const float inv1 = 1.0f / l[mi][1];
        const int q = q0 + w * 32 + mi * 16 + r0;
        #pragma unroll
        for (int ni = 0; ni < 4; ni++) {
            const int d = ni * 8 + 2 * quad;
            *reinterpret_cast<float2*>(&O[base + q * D_MODEL + d]) =
                make_float2(o[mi][ni][0] * inv0, o[mi][ni][1] * inv0);
            *reinterpret_cast<float2*>(&O[base + (q + 8) * D_MODEL + d]) =
                make_float2(o[mi][ni][2] * inv1, o[mi][ni][3] * inv1);
        }
    }
}

// ---------------------------------------------------------------------------
// Launch
// ---------------------------------------------------------------------------
extern "C" void kernel_launch(void* const* d_in, const int* in_sizes, int n_in,
                              void* d_out, int out_size)
{
    const float* x    = (const float*)d_in[0];
    const float* ln1s = (const float*)d_in[1];
    const float* ln1b = (const float*)d_in[2];
    const float* wq   = (const float*)d_in[3];
    const float* bq   = (const float*)d_in[4];
    const float* wk   = (const float*)d_in[5];
    const float* bk   = (const float*)d_in[6];
    const float* wv   = (const float*)d_in[7];
    const float* bv   = (const float*)d_in[8];
    const float* wo   = (const float*)d_in[9];
    const float* bo   = (const float*)d_in[10];
    const float* ln2s = (const float*)d_in[11];
    const float* ln2b = (const float*)d_in[12];
    const float* w1   = (const float*)d_in[13];
    const float* b1   = (const float*)d_in[14];
    const float* w2   = (const float*)d_in[15];
    const float* b2   = (const float*)d_in[16];

    float* X = (float*)d_out;

    float *normed, *q, *k, *v, *attn, *ffh;
    cudaGetSymbolAddress((void**)&normed, g_normed);
    cudaGetSymbolAddress((void**)&q,      g_q);
    cudaGetSymbolAddress((void**)&k,      g_k);
    cudaGetSymbolAddress((void**)&v,      g_v);
    cudaGetSymbolAddress((void**)&attn,   g_attn);
    cudaGetSymbolAddress((void**)&ffh,    g_ffh);

    cudaFuncSetAttribute(gemm_kernel<false, true>,
                         cudaFuncAttributeMaxDynamicSharedMemorySize, GEMM_SMEM_BYTES);
    cudaFuncSetAttribute(gemm_kernel<true, false>,
                         cudaFuncAttributeMaxDynamicSharedMemorySize, GEMM_SMEM_BYTES);
    cudaFuncSetAttribute(qkv_kernel,
                         cudaFuncAttributeMaxDynamicSharedMemorySize, GEMM_SMEM_BYTES);
    cudaFuncSetAttribute(attn_kernel,
                         cudaFuncAttributeMaxDynamicSharedMemorySize, ATTN_SMEM_BYTES);

    cudaMemcpyAsync(X, x, (size_t)NTOK * D_MODEL * sizeof(float),
                    cudaMemcpyDeviceToDevice);

    const dim3 gemm_dd(D_MODEL / 64, NTOK / 64);      // (4, 128)
    const dim3 gemm_df(D_FF / 64,    NTOK / 64);      // (16, 128)
    const dim3 qkv_grid(D_MODEL / 64, NTOK / 64, 3);
    const dim3 attn_grid(SEQ / 256, N_HEADS, BATCH);  // (8, 8, 4) = 256

    for (int l = 0; l < N_LAYERS; l++) {
        const int wdd = l * D_MODEL * D_MODEL;
        ln_kernel<<<NTOK, 256>>>(X, ln1s + l * D_MODEL, ln1b + l * D_MODEL, normed);

        qkv_kernel<<<qkv_grid, 128, GEMM_SMEM_BYTES>>>(normed,
                                      wq + wdd, wk + wdd, wv + wdd,
                                      bq + l * D_MODEL, bk + l * D_MODEL, bv + l * D_MODEL,
                                      q, k, v);

        attn_kernel<<<attn_grid, 256, ATTN_SMEM_BYTES>>>(q, k, v, attn);

        gemm_kernel<false, true><<<gemm_dd, 128, GEMM_SMEM_BYTES>>>(
            attn, wo + wdd, bo + l * D_MODEL, X, D_MODEL, D_MODEL);

        ln_kernel<<<NTOK, 256>>>(X, ln2s + l * D_MODEL, ln2b + l * D_MODEL, normed);

        gemm_kernel<true, false><<<gemm_df, 128, GEMM_SMEM_BYTES>>>(
            normed, w1 + l * D_MODEL * D_FF, b1 + l * D_FF, ffh, D_MODEL, D_FF);
        gemm_kernel<false, true><<<gemm_dd, 128, GEMM_SMEM_BYTES>>>(
            ffh, w2 + l * D_FF * D_MODEL, b2 + l * D_MODEL, X, D_FF, D_MODEL);
    }
}

// round 7
// speedup vs baseline: 1.5662x; 1.5662x over previous
#include <cuda_runtime.h>
#include <cuda_fp16.h>
#include <math.h>
#include <stdint.h>

#define D_MODEL   256
#define N_LAYERS  6
#define N_HEADS   8
#define D_FF      1024
#define HEAD_DIM  32
#define BATCH     4
#define SEQ       2048
#define NTOK      (BATCH * SEQ)   // 8192

// ---------------------------------------------------------------------------
// Scratch (fp16 activations + fp16 weight shadows)
// ---------------------------------------------------------------------------
__device__ __align__(16) __half g_normed[NTOK * D_MODEL];
__device__ __align__(16) __half g_q[NTOK * D_MODEL];
__device__ __align__(16) __half g_k[NTOK * D_MODEL];
__device__ __align__(16) __half g_v[NTOK * D_MODEL];
__device__ __align__(16) __half g_attn[NTOK * D_MODEL];
__device__ __align__(16) __half g_ffh[NTOK * D_FF];

__device__ __align__(16) __half g_wq16[N_LAYERS * D_MODEL * D_MODEL];
__device__ __align__(16) __half g_wk16[N_LAYERS * D_MODEL * D_MODEL];
__device__ __align__(16) __half g_wv16[N_LAYERS * D_MODEL * D_MODEL];
__device__ __align__(16) __half g_wo16[N_LAYERS * D_MODEL * D_MODEL];
__device__ __align__(16) __half g_w116[N_LAYERS * D_MODEL * D_FF];
__device__ __align__(16) __half g_w216[N_LAYERS * D_FF * D_MODEL];

// ---------------------------------------------------------------------------
// Helpers
// ---------------------------------------------------------------------------
__device__ __forceinline__ uint32_t smem_u32(const void* p) {
    return (uint32_t)__cvta_generic_to_shared(p);
}
#define CPA16(dst_u32, src_ptr) \
    asm volatile("cp.async.cg.shared.global [%0], [%1], 16;\n" :: "r"(dst_u32), "l"(src_ptr))
#define CPA_COMMIT() asm volatile("cp.async.commit_group;\n" ::)
#define CPA_WAIT2()  asm volatile("cp.async.wait_group 2;\n" ::)
#define CPA_WAIT1()  asm volatile("cp.async.wait_group 1;\n" ::)
#define CPA_WAIT0()  asm volatile("cp.async.wait_group 0;\n" ::)

// HMMA m16n8k16 fp16 -> fp32 accum
__device__ __forceinline__ void mma_f16(float* c, const uint32_t* a, const uint32_t* b) {
    asm volatile(
        "mma.sync.aligned.m16n8k16.row.col.f32.f16.f16.f32 "
        "{%0,%1,%2,%3},{%4,%5,%6,%7},{%8,%9},{%0,%1,%2,%3};\n"
        : "+f"(c[0]), "+f"(c[1]), "+f"(c[2]), "+f"(c[3])
        : "r"(a[0]), "r"(a[1]), "r"(a[2]), "r"(a[3]),
          "r"(b[0]), "r"(b[1]));
}

__device__ __forceinline__ void ldsm4(uint32_t* r, uint32_t byte_addr) {
    asm volatile("ldmatrix.sync.aligned.m8n8.x4.shared.b16 {%0,%1,%2,%3}, [%4];\n"
        : "=r"(r[0]), "=r"(r[1]), "=r"(r[2]), "=r"(r[3]) : "r"(byte_addr));
}
__device__ __forceinline__ void ldsm4t(uint32_t* r, uint32_t byte_addr) {
    asm volatile("ldmatrix.sync.aligned.m8n8.x4.trans.shared.b16 {%0,%1,%2,%3}, [%4];\n"
        : "=r"(r[0]), "=r"(r[1]), "=r"(r[2]), "=r"(r[3]) : "r"(byte_addr));
}

__device__ __forceinline__ float ex2(float x) {
    float y;
    asm("ex2.approx.f32 %0, %1;" : "=f"(y) : "f"(x));
    return y;
}

// ---------------------------------------------------------------------------
// fp32 -> fp16 weight conversion (runs each launch; deterministic)
// ---------------------------------------------------------------------------
__global__ void __launch_bounds__(256) cvt_kernel(
    const float* __restrict__ in, __half* __restrict__ out, int n4)
{
    const int i = blockIdx.x * blockDim.x + threadIdx.x;
    if (i < n4) {
        float4 v = reinterpret_cast<const float4*>(in)[i];
        __half2 h0 = __floats2half2_rn(v.x, v.y);
        __half2 h1 = __floats2half2_rn(v.z, v.w);
        reinterpret_cast<__half2*>(out)[2 * i]     = h0;
        reinterpret_cast<__half2*>(out)[2 * i + 1] = h1;
    }
}

// ---------------------------------------------------------------------------
// LayerNorm: fp32 in, fp16 out
// ---------------------------------------------------------------------------
__global__ void __launch_bounds__(256) ln_kernel(
    const float* __restrict__ X, const float* __restrict__ S,
    const float* __restrict__ Bb, __half* __restrict__ Y)
{
    const int row = blockIdx.x;
    const int tid = threadIdx.x;
    const float v = X[row * D_MODEL + tid];

    __shared__ float red[16];
    float s1 = v, s2 = v * v;
    #pragma unroll
    for (int off = 16; off > 0; off >>= 1) {
        s1 += __shfl_xor_sync(0xffffffffu, s1, off);
        s2 += __shfl_xor_sync(0xffffffffu, s2, off);
    }
    const int w = tid >> 5;
    if ((tid & 31) == 0) { red[w] = s1; red[8 + w] = s2; }
    __syncthreads();
    float sum = 0.f, sq = 0.f;
    #pragma unroll
    for (int i = 0; i < 8; i++) { sum += red[i]; sq += red[8 + i]; }
    const float mu  = sum * (1.0f / D_MODEL);
    const float var = sq * (1.0f / D_MODEL) - mu * mu;
    const float inv = rsqrtf(var + 1e-5f);
    Y[row * D_MODEL + tid] = __float2half((v - mu) * inv * S[tid] + Bb[tid]);
}

// ---------------------------------------------------------------------------
// fp16 GEMM: block 64x64, BK=32, 128 threads (2m x 2n warps, 32x32/warp).
// A via ldmatrix.x4, W via ldmatrix.x4.trans. 3-stage cp.async.
// smem: 3*(64*40 + 32*72) halves = 29184 B
// MODE 0: fp16 out (*oscale). MODE 1: GELU + fp16 out. MODE 2: fp32 residual out.
// ---------------------------------------------------------------------------
#define GEMM_SMEM_BYTES (3 * (64 * 40 + 32 * 72) * 2)

template <int MODE>
__device__ __forceinline__ void gemm16_body(
    const __half* __restrict__ A, const __half* __restrict__ W,
    const float* __restrict__ bias, void* Cv, int K, int M, float oscale)
{
    extern __shared__ __align__(16) __half smexh[];
    __half* As = smexh;                  // [3][64*40]
    __half* Ws = smexh + 3 * 64 * 40;    // [3][32*72]

    const int tid  = threadIdx.x;
    const int lane = tid & 31;
    const int wid  = tid >> 5;
    const int warp_m = wid >> 1;
    const int warp_n = wid & 1;
    const int r0   = lane >> 2;
    const int quad = lane & 3;
    const int row0 = blockIdx.y * 64;
    const int col0 = blockIdx.x * 64;

    const int lm_row  = lane & 15;
    const int lm_col8 = (lane >> 4) << 3;

    float acc[2][4][4] = {};

    auto load_stage = [&](int k0, int s) {
        __half* Asb = As + s * (64 * 40);
        #pragma unroll
        for (int i = 0; i < 2; i++) {
            int e = tid + i * 128;         // 0..255
            int r = e >> 2, c8 = e & 3;
            CPA16(smem_u32(&Asb[r * 40 + c8 * 8]),
                  A + (size_t)(row0 + r) * K + k0 + c8 * 8);
        }
        __half* Wsb = Ws + s * (32 * 72);
        #pragma unroll
        for (int i = 0; i < 2; i++) {
            int e = tid + i * 128;
            int r = e >> 3, c8 = e & 7;    // 32 rows x 8 segs
            CPA16(smem_u32(&Wsb[r * 72 + c8 * 8]),
                  W + (size_t)(k0 + r) * M + col0 + c8 * 8);
        }
        CPA_COMMIT();
    };

    const int nk = K >> 5;
    load_stage(0, 0);
    load_stage(32, 1);

    for (int it = 0; it < nk; ++it) {
        const int s = it % 3;
        if (it + 2 < nk)      { load_stage((it + 2) * 32, (it + 2) % 3); CPA_WAIT2(); }
        else if (it + 1 < nk) { CPA_WAIT1(); }
        else                  { CPA_WAIT0(); }
        __syncthreads();

        const __half* Asb = As + s * (64 * 40);
        const __half* Wsb = Ws + s * (32 * 72);

        #pragma unroll
        for (int ks = 0; ks < 2; ks++) {   // two k=16 steps
            uint32_t a[2][4], b[2][4];
            #pragma unroll
            for (int mi = 0; mi < 2; mi++) {
                const int rb = warp_m * 32 + mi * 16;
                ldsm4(a[mi], smem_u32(&Asb[(rb + lm_row) * 40 + ks * 16 + lm_col8]));
            }
            #pragma unroll
            for (int ni2 = 0; ni2 < 2; ni2++) {
                ldsm4t(b[ni2], smem_u32(&Wsb[(ks * 16 + lm_row) * 72 +
                                             warp_n * 32 + ni2 * 16 + lm_col8]));
            }
            #pragma unroll
            for (int mi = 0; mi < 2; mi++)
                #pragma unroll
                for (int ni2 = 0; ni2 < 2; ni2++) {
                    mma_f16(acc[mi][2 * ni2],     a[mi], &b[ni2][0]);
                    mma_f16(acc[mi][2 * ni2 + 1], a[mi], &b[ni2][2]);
                }
        }
        __syncthreads();
    }

    #pragma unroll
    for (int mi = 0; mi < 2; mi++) {
        #pragma unroll
        for (int ni = 0; ni < 4; ni++) {
            const int r = row0 + warp_m * 32 + mi * 16 + r0;
            const int c = col0 + warp_n * 32 + ni * 8 + 2 * quad;
            const float bx = bias[c], by = bias[c + 1];
            float v0 = acc[mi][ni][0] + bx;
            float v1 = acc[mi][ni][1] + by;
            float v2 = acc[mi][ni][2] + bx;
            float v3 = acc[mi][ni][3] + by;
            if (MODE == 1) {
                v0 = 0.5f * v0 * (1.0f + erff(v0 * 0.70710678118654752f));
                v1 = 0.5f * v1 * (1.0f + erff(v1 * 0.70710678118654752f));
                v2 = 0.5f * v2 * (1.0f + erff(v2 * 0.70710678118654752f));
                v3 = 0.5f * v3 * (1.0f + erff(v3 * 0.70710678118654752f));
            }
            if (MODE == 2) {
                float* Cf = (float*)Cv;
                float2 e0 = *reinterpret_cast<const float2*>(&Cf[(size_t)r * M + c]);
                float2 e1 = *reinterpret_cast<const float2*>(&Cf[(size_t)(r + 8) * M + c]);
                *reinterpret_cast<float2*>(&Cf[(size_t)r * M + c]) =
                    make_float2(v0 + e0.x, v1 + e0.y);
                *reinterpret_cast<float2*>(&Cf[(size_t)(r + 8) * M + c]) =
                    make_float2(v2 + e1.x, v3 + e1.y);
            } else {
                __half* Ch = (__half*)Cv;
                *reinterpret_cast<__half2*>(&Ch[(size_t)r * M + c]) =
                    __floats2half2_rn(v0 * oscale, v1 * oscale);
                *reinterpret_cast<__half2*>(&Ch[(size_t)(r + 8) * M + c]) =
                    __floats2half2_rn(v2 * oscale, v3 * oscale);
            }
        }
    }
}

template <int MODE>
__global__ void __launch_bounds__(128) gemm16_kernel(
    const __half* __restrict__ A, const __half* __restrict__ W,
    const float* __restrict__ bias, void* Cv, int K, int M, float oscale)
{
    gemm16_body<MODE>(A, W, bias, Cv, K, M, oscale);
}

__global__ void __launch_bounds__(128) qkv16_kernel(
    const __half* __restrict__ A,
    const __half* __restrict__ wq, const __half* __restrict__ wk, const __half* __restrict__ wv,
    const float* __restrict__ bq, const float* __restrict__ bk, const float* __restrict__ bv,
    __half* __restrict__ q, __half* __restrict__ k, __half* __restrict__ v, float qscale)
{
    const __half* W; const float* B; __half* C; float os;
    if (blockIdx.z == 0)      { W = wq; B = bq; C = q; os = qscale; }
    else if (blockIdx.z == 1) { W = wk; B = bk; C = k; os = 1.0f; }
    else                      { W = wv; B = bv; C = v; os = 1.0f; }
    gemm16_body<0>(A, W, B, (void*)C, D_MODEL, D_MODEL, os);
}

// ---------------------------------------------------------------------------
// Flash attention fp16: CTA = 128 queries, 4 warps (warp 32q), KV tiles 64,
// 3-stage cp.async. Q pre-scaled by log2(e)/sqrt(32) in qkv. P/V fp16 MMA.
// smem halves: Q[128*40] + 3*K[64*40] + 3*V[64*40] + P[128*72] = 29696 -> 59392 B
// ---------------------------------------------------------------------------
#define ATTN_SMEM_BYTES ((128 * 40 + 3 * (64 * 40) * 2 + 128 * 72) * 2)

__global__ void __launch_bounds__(128) attn_kernel(
    const __half* __restrict__ Q, const __half* __restrict__ K,
    const __half* __restrict__ V, __half* __restrict__ O)
{
    extern __shared__ __align__(16) __half smexh[];
    __half* Qs = smexh;                    // 128*40
    __half* Ks = Qs + 128 * 40;            // [3][64*40]
    __half* Vs = Ks + 3 * 64 * 40;         // [3][64*40]
    __half* Ps = Vs + 3 * 64 * 40;         // 128*72

    const int tid  = threadIdx.x;
    const int lane = tid & 31;
    const int w    = tid >> 5;
    const int r0   = lane >> 2;
    const int quad = lane & 3;
    const int q0   = blockIdx.x * 128;
    const int h    = blockIdx.y;
    const int b    = blockIdx.z;
    const int base = (b * SEQ) * D_MODEL + h * HEAD_DIM;

    const int lm_row  = lane & 15;
    const int lm_col8 = (lane >> 4) << 3;
    // non-trans B pattern (K): rows = keys, col = k-dim segment
    const int lmb_row  = (lane & 7) + ((lane >> 4) << 3);
    const int lmb_col8 = (((lane >> 3) & 1) << 3);

    // Q first (own commit group), then two KV stages
    {
        #pragma unroll
        for (int i = 0; i < 4; i++) {
            int e = tid + i * 128;          // 0..511
            int r = e >> 2, c8 = e & 3;
            CPA16(smem_u32(&Qs[r * 40 + c8 * 8]),
                  &Q[base + (q0 + r) * D_MODEL + c8 * 8]);
        }
        CPA_COMMIT();
    }

    auto load_kv = [&](int kt, int s) {
        __half* Ksb = Ks + s * (64 * 40);
        __half* Vsb = Vs + s * (64 * 40);
        #pragma unroll
        for (int i = 0; i < 2; i++) {
            const int e = tid + i * 128;    // 0..255
            const int r = e >> 2, c8 = e & 3;
            CPA16(smem_u32(&Ksb[r * 40 + c8 * 8]), &K[base + (kt + r) * D_MODEL + c8 * 8]);
            CPA16(smem_u32(&Vsb[r * 40 + c8 * 8]), &V[base + (kt + r) * D_MODEL + c8 * 8]);
        }
        CPA_COMMIT();
    };

    load_kv(0, 0);
    load_kv(64, 1);

    // Wait for Q (all but the newest two groups), hoist Q frags
    CPA_WAIT2();
    __syncthreads();
    uint32_t qf[2][2][4];                  // [mi][kstep][frag]
    #pragma unroll
    for (int mi = 0; mi < 2; mi++) {
        const int rb = w * 32 + mi * 16;
        #pragma unroll
        for (int ks = 0; ks < 2; ks++)
            ldsm4(qf[mi][ks], smem_u32(&Qs[(rb + lm_row) * 40 + ks * 16 + lm_col8]));
    }

    float m[2][2], l[2][2], o[2][4][4] = {};
    #pragma unroll
    for (int mi = 0; mi < 2; mi++) { m[mi][0] = m[mi][1] = -1e30f; l[mi][0] = l[mi][1] = 0.f; }

    const int NIT = SEQ / 64;
    for (int it = 0; it < NIT; ++it) {
        const int s = it % 3;
        if (it + 2 < NIT)      { load_kv((it + 2) * 64, (it + 2) % 3); CPA_WAIT2(); }
        else if (it + 1 < NIT) { CPA_WAIT1(); }
        else                   { CPA_WAIT0(); }
        __syncthreads();

        const __half* Ksb = Ks + s * (64 * 40);
        const __half* Vsb = Vs + s * (64 * 40);

        // S = Q K^T : warp 32x64, scores pre-scaled to log2 domain via Q
        float sc[2][8][4] = {};
        #pragma unroll
        for (int ks = 0; ks < 2; ks++) {
            uint32_t bfr[4][4];
            #pragma unroll
            for (int nq = 0; nq < 4; nq++)
                ldsm4(bfr[nq], smem_u32(&Ksb[(nq * 16 + lmb_row) * 40 +
                                             ks * 16 + lmb_col8]));
            #pragma unroll
            for (int mi = 0; mi < 2; mi++)
                #pragma unroll
                for (int nq = 0; nq < 4; nq++) {
                    mma_f16(sc[mi][2 * nq],     qf[mi][ks], &bfr[nq][0]);
                    mma_f16(sc[mi][2 * nq + 1], qf[mi][ks], &bfr[nq][2]);
                }
        }

        // Online softmax (base-2), P -> smem fp16
        #pragma unroll
        for (int mi = 0; mi < 2; mi++) {
            const int rb = w * 32 + mi * 16 + r0;
            float mt0 = -1e30f, mt1 = -1e30f;
            #pragma unroll
            for (int ni = 0; ni < 8; ni++) {
                mt0 = fmaxf(mt0, fmaxf(sc[mi][ni][0], sc[mi][ni][1]));
                mt1 = fmaxf(mt1, fmaxf(sc[mi][ni][2], sc[mi][ni][3]));
            }
            #pragma unroll
            for (int off = 1; off < 4; off <<= 1) {
                mt0 = fmaxf(mt0, __shfl_xor_sync(0xffffffffu, mt0, off));
                mt1 = fmaxf(mt1, __shfl_xor_sync(0xffffffffu, mt1, off));
            }
            const float mn0 = fmaxf(m[mi][0], mt0);
            const float mn1 = fmaxf(m[mi][1], mt1);
            const float alpha0 = ex2(m[mi][0] - mn0);
            const float alpha1 = ex2(m[mi][1] - mn1);
            m[mi][0] = mn0; m[mi][1] = mn1;

            float rs0 = 0.f, rs1 = 0.f;
            #pragma unroll
            for (int ni = 0; ni < 8; ni++) {
                const float p00 = ex2(sc[mi][ni][0] - mn0);
                const float p01 = ex2(sc[mi][ni][1] - mn0);
                const float p10 = ex2(sc[mi][ni][2] - mn1);
                const float p11 = ex2(sc[mi][ni][3] - mn1);
                rs0 += p00 + p01;
                rs1 += p10 + p11;
                const int col = ni * 8 + 2 * quad;
                *reinterpret_cast<__half2*>(&Ps[rb * 72 + col])       = __floats2half2_rn(p00, p01);
                *reinterpret_cast<__half2*>(&Ps[(rb + 8) * 72 + col]) = __floats2half2_rn(p10, p11);
            }
            #pragma unroll
            for (int off = 1; off < 4; off <<= 1) {
                rs0 += __shfl_xor_sync(0xffffffffu, rs0, off);
                rs1 += __shfl_xor_sync(0xffffffffu, rs1, off);
            }
            l[mi][0] = l[mi][0] * alpha0 + rs0;
            l[mi][1] = l[mi][1] * alpha1 + rs1;
            #pragma unroll
            for (int ni = 0; ni < 4; ni++) {
                o[mi][ni][0] *= alpha0; o[mi][ni][1] *= alpha0;
                o[mi][ni][2] *= alpha1; o[mi][ni][3] *= alpha1;
            }
        }
        __syncwarp();   // P rows are warp-private: order write -> ldmatrix read

        // O += P @ V : 4 k-steps of 16 keys
        #pragma unroll
        for (int ks = 0; ks < 4; ks++) {
            uint32_t a[2][4], b[2][4];
            #pragma unroll
            for (int mi = 0; mi < 2; mi++) {
                const int rb = w * 32 + mi * 16;
                ldsm4(a[mi], smem_u32(&Ps[(rb + lm_row) * 72 + ks * 16 + lm_col8]));
            }
            #pragma unroll
            for (int ni2 = 0; ni2 < 2; ni2++)
                ldsm4t(b[ni2], smem_u32(&Vsb[(ks * 16 + lm_row) * 40 +
                                             ni2 * 16 + lm_col8]));
            #pragma unroll
            for (int mi = 0; mi < 2; mi++)
                #pragma unroll
                for (int ni2 = 0; ni2 < 2; ni2++) {
                    mma_f16(o[mi][2 * ni2],     a[mi], &b[ni2][0]);
                    mma_f16(o[mi][2 * ni2 + 1], a[mi], &b[ni2][2]);
                }
        }
        __syncthreads();   // stage s fully consumed before it is overwritten
    }

    #pragma unroll
    for (int mi = 0; mi < 2; mi++) {
        const float inv0 = 1.0f / l[mi][0];
        const float inv1 = 1.0f / l[mi][1];
        const int q = q0 + w * 32 + mi * 16 + r0;
        #pragma unroll
        for (int ni = 0; ni < 4; ni++) {
            const int d = ni * 8 + 2 * quad;
            *reinterpret_cast<__half2*>(&O[base + q * D_MODEL + d]) =
                __floats2half2_rn(o[mi][ni][0] * inv0, o[mi][ni][1] * inv0);
            *reinterpret_cast<__half2*>(&O[base + (q + 8) * D_MODEL + d]) =
                __floats2half2_rn(o[mi][ni][2] * inv1, o[mi][ni][3] * inv1);
        }
    }
}

// ---------------------------------------------------------------------------
// Launch
// ---------------------------------------------------------------------------
extern "C" void kernel_launch(void* const* d_in, const int* in_sizes, int n_in,
                              void* d_out, int out_size)
{
    const float* x    = (const float*)d_in[0];
    const float* ln1s = (const float*)d_in[1];
    const float* ln1b = (const float*)d_in[2];
    const float* wq   = (const float*)d_in[3];
    const float* bq   = (const float*)d_in[4];
    const float* wk   = (const float*)d_in[5];
    const float* bk   = (const float*)d_in[6];
    const float* wv   = (const float*)d_in[7];
    const float* bv   = (const float*)d_in[8];
    const float* wo   = (const float*)d_in[9];
    const float* bo   = (const float*)d_in[10];
    const float* ln2s = (const float*)d_in[11];
    const float* ln2b = (const float*)d_in[12];
    const float* w1   = (const float*)d_in[13];
    const float* b1   = (const float*)d_in[14];
    const float* w2   = (const float*)d_in[15];
    const float* b2   = (const float*)d_in[16];

    float* X = (float*)d_out;

    __half *normed, *q, *k, *v, *attn, *ffh;
    __half *wq16, *wk16, *wv16, *wo16, *w116, *w216;
    cudaGetSymbolAddress((void**)&normed, g_normed);
    cudaGetSymbolAddress((void**)&q,      g_q);
    cudaGetSymbolAddress((void**)&k,      g_k);
    cudaGetSymbolAddress((void**)&v,      g_v);
    cudaGetSymbolAddress((void**)&attn,   g_attn);
    cudaGetSymbolAddress((void**)&ffh,    g_ffh);
    cudaGetSymbolAddress((void**)&wq16,   g_wq16);
    cudaGetSymbolAddress((void**)&wk16,   g_wk16);
    cudaGetSymbolAddress((void**)&wv16,   g_wv16);
    cudaGetSymbolAddress((void**)&wo16,   g_wo16);
    cudaGetSymbolAddress((void**)&w116,   g_w116);
    cudaGetSymbolAddress((void**)&w216,   g_w216);

    cudaFuncSetAttribute(attn_kernel,
                         cudaFuncAttributeMaxDynamicSharedMemorySize, ATTN_SMEM_BYTES);

    cudaMemcpyAsync(X, x, (size_t)NTOK * D_MODEL * sizeof(float),
                    cudaMemcpyDeviceToDevice);

    // Convert all weights fp32 -> fp16 (per launch; deterministic)
    {
        const int n_dd = N_LAYERS * D_MODEL * D_MODEL;   // 393216
        const int n_df = N_LAYERS * D_MODEL * D_FF;      // 1572864
        cvt_kernel<<<(n_dd / 4 + 255) / 256, 256>>>(wq, wq16, n_dd / 4);
        cvt_kernel<<<(n_dd / 4 + 255) / 256, 256>>>(wk, wk16, n_dd / 4);
        cvt_kernel<<<(n_dd / 4 + 255) / 256, 256>>>(wv, wv16, n_dd / 4);
        cvt_kernel<<<(n_dd / 4 + 255) / 256, 256>>>(wo, wo16, n_dd / 4);
        cvt_kernel<<<(n_df / 4 + 255) / 256, 256>>>(w1, w116, n_df / 4);
        cvt_kernel<<<(n_df / 4 + 255) / 256, 256>>>(w2, w216, n_df / 4);
    }

    const float qscale = 0.17677669529663687f * 1.4426950408889634f;  // /sqrt(32)*log2(e)

    const dim3 gemm_dd(D_MODEL / 64, NTOK / 64);      // (4, 128)
    const dim3 gemm_df(D_FF / 64,    NTOK / 64);      // (16, 128)
    const dim3 qkv_grid(D_MODEL / 64, NTOK / 64, 3);
    const dim3 attn_grid(SEQ / 128, N_HEADS, BATCH);  // (16, 8, 4)

    for (int ly = 0; ly < N_LAYERS; ly++) {
        const int wdd = ly * D_MODEL * D_MODEL;
        const int wdf = ly * D_MODEL * D_FF;

        ln_kernel<<<NTOK, 256>>>(X, ln1s + ly * D_MODEL, ln1b + ly * D_MODEL, normed);

        qkv16_kernel<<<qkv_grid, 128, GEMM_SMEM_BYTES>>>(
            normed, wq16 + wdd, wk16 + wdd, wv16 + wdd,
            bq + ly * D_MODEL, bk + ly * D_MODEL, bv + ly * D_MODEL,
            q, k, v, qscale);

        attn_kernel<<<attn_grid, 128, ATTN_SMEM_BYTES>>>(q, k, v, attn);

        gemm16_kernel<2><<<gemm_dd, 128, GEMM_SMEM_BYTES>>>(
            attn, wo16 + wdd, bo + ly * D_MODEL, (void*)X, D_MODEL, D_MODEL, 1.0f);

        ln_kernel<<<NTOK, 256>>>(X, ln2s + ly * D_MODEL, ln2b + ly * D_MODEL, normed);

        gemm16_kernel<1><<<gemm_df, 128, GEMM_SMEM_BYTES>>>(
            normed, w116 + wdf, b1 + ly * D_FF, (void*)ffh, D_MODEL, D_FF, 1.0f);

        gemm16_kernel<2><<<gemm_dd, 128, GEMM_SMEM_BYTES>>>(
            ffh, w216 + wdf, b2 + ly * D_MODEL, (void*)X, D_FF, D_MODEL, 1.0f);
    }
}

// round 8
// speedup vs baseline: 1.8131x; 1.1577x over previous
#include <cuda_runtime.h>
#include <cuda_fp16.h>
#include <math.h>
#include <stdint.h>

#define D_MODEL   256
#define N_LAYERS  6
#define N_HEADS   8
#define D_FF      1024
#define HEAD_DIM  32
#define BATCH     4
#define SEQ       2048
#define NTOK      (BATCH * SEQ)   // 8192

// ---------------------------------------------------------------------------
// Scratch (fp16 activations + fp16 weight shadows)
// ---------------------------------------------------------------------------
__device__ __align__(16) __half g_normed[NTOK * D_MODEL];
__device__ __align__(16) __half g_q[NTOK * D_MODEL];
__device__ __align__(16) __half g_k[NTOK * D_MODEL];
__device__ __align__(16) __half g_v[NTOK * D_MODEL];
__device__ __align__(16) __half g_attn[NTOK * D_MODEL];
__device__ __align__(16) __half g_ffh[NTOK * D_FF];

__device__ __align__(16) __half g_wq16[N_LAYERS * D_MODEL * D_MODEL];
__device__ __align__(16) __half g_wk16[N_LAYERS * D_MODEL * D_MODEL];
__device__ __align__(16) __half g_wv16[N_LAYERS * D_MODEL * D_MODEL];
__device__ __align__(16) __half g_wo16[N_LAYERS * D_MODEL * D_MODEL];
__device__ __align__(16) __half g_w116[N_LAYERS * D_MODEL * D_FF];
__device__ __align__(16) __half g_w216[N_LAYERS * D_FF * D_MODEL];

// ---------------------------------------------------------------------------
// Helpers
// ---------------------------------------------------------------------------
__device__ __forceinline__ uint32_t smem_u32(const void* p) {
    return (uint32_t)__cvta_generic_to_shared(p);
}
#define CPA16(dst_u32, src_ptr) \
    asm volatile("cp.async.cg.shared.global [%0], [%1], 16;\n" :: "r"(dst_u32), "l"(src_ptr))
#define CPA_COMMIT() asm volatile("cp.async.commit_group;\n" ::)
#define CPA_WAIT2()  asm volatile("cp.async.wait_group 2;\n" ::)
#define CPA_WAIT1()  asm volatile("cp.async.wait_group 1;\n" ::)
#define CPA_WAIT0()  asm volatile("cp.async.wait_group 0;\n" ::)

// HMMA m16n8k16 fp16 -> fp32 accum
__device__ __forceinline__ void mma_f16(float* c, const uint32_t* a, const uint32_t* b) {
    asm volatile(
        "mma.sync.aligned.m16n8k16.row.col.f32.f16.f16.f32 "
        "{%0,%1,%2,%3},{%4,%5,%6,%7},{%8,%9},{%0,%1,%2,%3};\n"
        : "+f"(c[0]), "+f"(c[1]), "+f"(c[2]), "+f"(c[3])
        : "r"(a[0]), "r"(a[1]), "r"(a[2]), "r"(a[3]),
          "r"(b[0]), "r"(b[1]));
}

__device__ __forceinline__ void ldsm4(uint32_t* r, uint32_t byte_addr) {
    asm volatile("ldmatrix.sync.aligned.m8n8.x4.shared.b16 {%0,%1,%2,%3}, [%4];\n"
        : "=r"(r[0]), "=r"(r[1]), "=r"(r[2]), "=r"(r[3]) : "r"(byte_addr));
}
__device__ __forceinline__ void ldsm4t(uint32_t* r, uint32_t byte_addr) {
    asm volatile("ldmatrix.sync.aligned.m8n8.x4.trans.shared.b16 {%0,%1,%2,%3}, [%4];\n"
        : "=r"(r[0]), "=r"(r[1]), "=r"(r[2]), "=r"(r[3]) : "r"(byte_addr));
}

__device__ __forceinline__ float ex2(float x) {
    float y;
    asm("ex2.approx.f32 %0, %1;" : "=f"(y) : "f"(x));
    return y;
}
// pack two floats to half2 then 2^x elementwise (1 MUFU for 2 values)
__device__ __forceinline__ uint32_t ex2h2(float a, float b) {
    __half2 h = __floats2half2_rn(a, b);
    uint32_t hu = *reinterpret_cast<uint32_t*>(&h);
    uint32_t r;
    asm("ex2.approx.f16x2 %0, %1;" : "=r"(r) : "r"(hu));
    return r;
}

// ---------------------------------------------------------------------------
// Merged fp32 -> fp16 weight conversion (one launch for all 6 weights)
// ---------------------------------------------------------------------------
#define DD4 (N_LAYERS * D_MODEL * D_MODEL / 4)   // 98304
#define DF4 (N_LAYERS * D_MODEL * D_FF / 4)      // 393216
#define TOT4 (4 * DD4 + 2 * DF4)                 // 1179648

__global__ void __launch_bounds__(256) cvt_all_kernel(
    const float* __restrict__ wq, const float* __restrict__ wk,
    const float* __restrict__ wv, const float* __restrict__ wo,
    const float* __restrict__ w1, const float* __restrict__ w2,
    __half* __restrict__ wq16, __half* __restrict__ wk16,
    __half* __restrict__ wv16, __half* __restrict__ wo16,
    __half* __restrict__ w116, __half* __restrict__ w216)
{
    const int i = blockIdx.x * blockDim.x + threadIdx.x;
    if (i >= TOT4) return;
    const float* src; __half* dst; int off;
    if (i < DD4)          { src = wq; dst = wq16; off = i; }
    else if (i < 2 * DD4) { src = wk; dst = wk16; off = i - DD4; }
    else if (i < 3 * DD4) { src = wv; dst = wv16; off = i - 2 * DD4; }
    else if (i < 4 * DD4) { src = wo; dst = wo16; off = i - 3 * DD4; }
    else if (i < 4 * DD4 + DF4) { src = w1; dst = w116; off = i - 4 * DD4; }
    else                  { src = w2; dst = w216; off = i - 4 * DD4 - DF4; }
    float4 v = reinterpret_cast<const float4*>(src)[off];
    __half2 h0 = __floats2half2_rn(v.x, v.y);
    __half2 h1 = __floats2half2_rn(v.z, v.w);
    reinterpret_cast<__half2*>(dst)[2 * off]     = h0;
    reinterpret_cast<__half2*>(dst)[2 * off + 1] = h1;
}

// ---------------------------------------------------------------------------
// LayerNorm: warp per row, float4 loads, fp16 out. Block = 8 warps = 8 rows.
// ---------------------------------------------------------------------------
__global__ void __launch_bounds__(256) ln_kernel(
    const float* __restrict__ X, const float* __restrict__ S,
    const float* __restrict__ Bb, __half* __restrict__ Y)
{
    const int row  = blockIdx.x * 8 + (threadIdx.x >> 5);
    const int lane = threadIdx.x & 31;
    const int c0   = lane * 8;

    const float4 a = *reinterpret_cast<const float4*>(&X[row * D_MODEL + c0]);
    const float4 b = *reinterpret_cast<const float4*>(&X[row * D_MODEL + c0 + 4]);

    float s1 = a.x + a.y + a.z + a.w + b.x + b.y + b.z + b.w;
    float s2 = a.x * a.x + a.y * a.y + a.z * a.z + a.w * a.w
             + b.x * b.x + b.y * b.y + b.z * b.z + b.w * b.w;
    #pragma unroll
    for (int off = 16; off > 0; off >>= 1) {
        s1 += __shfl_xor_sync(0xffffffffu, s1, off);
        s2 += __shfl_xor_sync(0xffffffffu, s2, off);
    }
    const float mu  = s1 * (1.0f / D_MODEL);
    const float var = s2 * (1.0f / D_MODEL) - mu * mu;
    const float inv = rsqrtf(var + 1e-5f);

    const float4 sa = *reinterpret_cast<const float4*>(&S[c0]);
    const float4 sb = *reinterpret_cast<const float4*>(&S[c0 + 4]);
    const float4 ba = *reinterpret_cast<const float4*>(&Bb[c0]);
    const float4 bb = *reinterpret_cast<const float4*>(&Bb[c0 + 4]);

    __half2 h[4];
    h[0] = __floats2half2_rn((a.x - mu) * inv * sa.x + ba.x, (a.y - mu) * inv * sa.y + ba.y);
    h[1] = __floats2half2_rn((a.z - mu) * inv * sa.z + ba.z, (a.w - mu) * inv * sa.w + ba.w);
    h[2] = __floats2half2_rn((b.x - mu) * inv * sb.x + bb.x, (b.y - mu) * inv * sb.y + bb.y);
    h[3] = __floats2half2_rn((b.z - mu) * inv * sb.z + bb.z, (b.w - mu) * inv * sb.w + bb.w);
    *reinterpret_cast<uint4*>(&Y[row * D_MODEL + c0]) = *reinterpret_cast<uint4*>(h);
}

// ---------------------------------------------------------------------------
// fp16 GEMM: block 64x64, BK=32, 128 threads (2m x 2n warps, 32x32/warp).
// A via ldmatrix.x4, W via ldmatrix.x4.trans. 3-stage cp.async.
// MODE 0: fp16 out (*oscale). MODE 1: GELU + fp16 out. MODE 2: fp32 residual out.
// ---------------------------------------------------------------------------
#define GEMM_SMEM_BYTES (3 * (64 * 40 + 32 * 72) * 2)

template <int MODE>
__device__ __forceinline__ void gemm16_body(
    const __half* __restrict__ A, const __half* __restrict__ W,
    const float* __restrict__ bias, void* Cv, int K, int M, float oscale)
{
    extern __shared__ __align__(16) __half smexh[];
    __half* As = smexh;                  // [3][64*40]
    __half* Ws = smexh + 3 * 64 * 40;    // [3][32*72]

    const int tid  = threadIdx.x;
    const int lane = tid & 31;
    const int wid  = tid >> 5;
    const int warp_m = wid >> 1;
    const int warp_n = wid & 1;
    const int r0   = lane >> 2;
    const int quad = lane & 3;
    const int row0 = blockIdx.y * 64;
    const int col0 = blockIdx.x * 64;

    const int lm_row  = lane & 15;
    const int lm_col8 = (lane >> 4) << 3;

    float acc[2][4][4] = {};

    auto load_stage = [&](int k0, int s) {
        __half* Asb = As + s * (64 * 40);
        #pragma unroll
        for (int i = 0; i < 2; i++) {
            int e = tid + i * 128;
            int r = e >> 2, c8 = e & 3;
            CPA16(smem_u32(&Asb[r * 40 + c8 * 8]),
                  A + (size_t)(row0 + r) * K + k0 + c8 * 8);
        }
        __half* Wsb = Ws + s * (32 * 72);
        #pragma unroll
        for (int i = 0; i < 2; i++) {
            int e = tid + i * 128;
            int r = e >> 3, c8 = e & 7;
            CPA16(smem_u32(&Wsb[r * 72 + c8 * 8]),
                  W + (size_t)(k0 + r) * M + col0 + c8 * 8);
        }
        CPA_COMMIT();
    };

    const int nk = K >> 5;
    load_stage(0, 0);
    load_stage(32, 1);

    for (int it = 0; it < nk; ++it) {
        const int s = it % 3;
        if (it + 2 < nk)      { load_stage((it + 2) * 32, (it + 2) % 3); CPA_WAIT2(); }
        else if (it + 1 < nk) { CPA_WAIT1(); }
        else                  { CPA_WAIT0(); }
        __syncthreads();

        const __half* Asb = As + s * (64 * 40);
        const __half* Wsb = Ws + s * (32 * 72);

        #pragma unroll
        for (int ks = 0; ks < 2; ks++) {
            uint32_t a[2][4], b[2][4];
            #pragma unroll
            for (int mi = 0; mi < 2; mi++) {
                const int rb = warp_m * 32 + mi * 16;
                ldsm4(a[mi], smem_u32(&Asb[(rb + lm_row) * 40 + ks * 16 + lm_col8]));
            }
            #pragma unroll
            for (int ni2 = 0; ni2 < 2; ni2++) {
                ldsm4t(b[ni2], smem_u32(&Wsb[(ks * 16 + lm_row) * 72 +
                                             warp_n * 32 + ni2 * 16 + lm_col8]));
            }
            #pragma unroll
            for (int mi = 0; mi < 2; mi++)
                #pragma unroll
                for (int ni2 = 0; ni2 < 2; ni2++) {
                    mma_f16(acc[mi][2 * ni2],     a[mi], &b[ni2][0]);
                    mma_f16(acc[mi][2 * ni2 + 1], a[mi], &b[ni2][2]);
                }
        }
        __syncthreads();
    }

    #pragma unroll
    for (int mi = 0; mi < 2; mi++) {
        #pragma unroll
        for (int ni = 0; ni < 4; ni++) {
            const int r = row0 + warp_m * 32 + mi * 16 + r0;
            const int c = col0 + warp_n * 32 + ni * 8 + 2 * quad;
            const float bx = bias[c], by = bias[c + 1];
            float v0 = acc[mi][ni][0] + bx;
            float v1 = acc[mi][ni][1] + by;
            float v2 = acc[mi][ni][2] + bx;
            float v3 = acc[mi][ni][3] + by;
            if (MODE == 1) {
                v0 = 0.5f * v0 * (1.0f + erff(v0 * 0.70710678118654752f));
                v1 = 0.5f * v1 * (1.0f + erff(v1 * 0.70710678118654752f));
                v2 = 0.5f * v2 * (1.0f + erff(v2 * 0.70710678118654752f));
                v3 = 0.5f * v3 * (1.0f + erff(v3 * 0.70710678118654752f));
            }
            if (MODE == 2) {
                float* Cf = (float*)Cv;
                float2 e0 = *reinterpret_cast<const float2*>(&Cf[(size_t)r * M + c]);
                float2 e1 = *reinterpret_cast<const float2*>(&Cf[(size_t)(r + 8) * M + c]);
                *reinterpret_cast<float2*>(&Cf[(size_t)r * M + c]) =
                    make_float2(v0 + e0.x, v1 + e0.y);
                *reinterpret_cast<float2*>(&Cf[(size_t)(r + 8) * M + c]) =
                    make_float2(v2 + e1.x, v3 + e1.y);
            } else {
                __half* Ch = (__half*)Cv;
                *reinterpret_cast<__half2*>(&Ch[(size_t)r * M + c]) =
                    __floats2half2_rn(v0 * oscale, v1 * oscale);
                *reinterpret_cast<__half2*>(&Ch[(size_t)(r + 8) * M + c]) =
                    __floats2half2_rn(v2 * oscale, v3 * oscale);
            }
        }
    }
}

template <int MODE>
__global__ void __launch_bounds__(128) gemm16_kernel(
    const __half* __restrict__ A, const __half* __restrict__ W,
    const float* __restrict__ bias, void* Cv, int K, int M, float oscale)
{
    gemm16_body<MODE>(A, W, bias, Cv, K, M, oscale);
}

__global__ void __launch_bounds__(128) qkv16_kernel(
    const __half* __restrict__ A,
    const __half* __restrict__ wq, const __half* __restrict__ wk, const __half* __restrict__ wv,
    const float* __restrict__ bq, const float* __restrict__ bk, const float* __restrict__ bv,
    __half* __restrict__ q, __half* __restrict__ k, __half* __restrict__ v, float qscale)
{
    const __half* W; const float* B; __half* C; float os;
    if (blockIdx.z == 0)      { W = wq; B = bq; C = q; os = qscale; }
    else if (blockIdx.z == 1) { W = wk; B = bk; C = k; os = 1.0f; }
    else                      { W = wv; B = bv; C = v; os = 1.0f; }
    gemm16_body<0>(A, W, B, (void*)C, D_MODEL, D_MODEL, os);
}

// ---------------------------------------------------------------------------
// Flash attention fp16: CTA = 128 queries, 4 warps (warp 32q), KV tiles 64,
// 3-stage cp.async. Softmax via ex2.f16x2; row-sum l via constant ones
// B-fragment appended to P@V (l rescales with O automatically).
// ---------------------------------------------------------------------------
#define ATTN_SMEM_BYTES ((128 * 40 + 3 * (64 * 40) * 2 + 128 * 72) * 2)

__global__ void __launch_bounds__(128, 3) attn_kernel(
    const __half* __restrict__ Q, const __half* __restrict__ K,
    const __half* __restrict__ V, __half* __restrict__ O)
{
    extern __shared__ __align__(16) __half smexh[];
    __half* Qs = smexh;                    // 128*40
    __half* Ks = Qs + 128 * 40;            // [3][64*40]
    __half* Vs = Ks + 3 * 64 * 40;         // [3][64*40]
    __half* Ps = Vs + 3 * 64 * 40;         // 128*72

    const int tid  = threadIdx.x;
    const int lane = tid & 31;
    const int w    = tid >> 5;
    const int r0   = lane >> 2;
    const int quad = lane & 3;
    const int q0   = blockIdx.x * 128;
    const int h    = blockIdx.y;
    const int b    = blockIdx.z;
    const int base = (b * SEQ) * D_MODEL + h * HEAD_DIM;

    const int lm_row  = lane & 15;
    const int lm_col8 = (lane >> 4) << 3;
    const int lmb_row  = (lane & 7) + ((lane >> 4) << 3);
    const int lmb_col8 = (((lane >> 3) & 1) << 3);

    {
        #pragma unroll
        for (int i = 0; i < 4; i++) {
            int e = tid + i * 128;
            int r = e >> 2, c8 = e & 3;
            CPA16(smem_u32(&Qs[r * 40 + c8 * 8]),
                  &Q[base + (q0 + r) * D_MODEL + c8 * 8]);
        }
        CPA_COMMIT();
    }

    auto load_kv = [&](int kt, int s) {
        __half* Ksb = Ks + s * (64 * 40);
        __half* Vsb = Vs + s * (64 * 40);
        #pragma unroll
        for (int i = 0; i < 2; i++) {
            const int e = tid + i * 128;
            const int r = e >> 2, c8 = e & 3;
            CPA16(smem_u32(&Ksb[r * 40 + c8 * 8]), &K[base + (kt + r) * D_MODEL + c8 * 8]);
            CPA16(smem_u32(&Vsb[r * 40 + c8 * 8]), &V[base + (kt + r) * D_MODEL + c8 * 8]);
        }
        CPA_COMMIT();
    };

    load_kv(0, 0);
    load_kv(64, 1);

    CPA_WAIT2();
    __syncthreads();
    uint32_t qf[2][2][4];
    #pragma unroll
    for (int mi = 0; mi < 2; mi++) {
        const int rb = w * 32 + mi * 16;
        #pragma unroll
        for (int ks = 0; ks < 2; ks++)
            ldsm4(qf[mi][ks], smem_u32(&Qs[(rb + lm_row) * 40 + ks * 16 + lm_col8]));
    }

    float m[2][2], o[2][4][4] = {}, oE[2][4] = {};
    #pragma unroll
    for (int mi = 0; mi < 2; mi++) { m[mi][0] = m[mi][1] = -1e30f; }

    const uint32_t onesfrag[2] = {0x3C003C00u, 0x3C003C00u};  // 8-wide ones B-tile

    const int NIT = SEQ / 64;
    for (int it = 0; it < NIT; ++it) {
        const int s = it % 3;
        if (it + 2 < NIT)      { load_kv((it + 2) * 64, (it + 2) % 3); CPA_WAIT2(); }
        else if (it + 1 < NIT) { CPA_WAIT1(); }
        else                   { CPA_WAIT0(); }
        __syncthreads();

        const __half* Ksb = Ks + s * (64 * 40);
        const __half* Vsb = Vs + s * (64 * 40);

        // S = Q K^T (scores already in log2 domain via pre-scaled Q)
        float sc[2][8][4] = {};
        #pragma unroll
        for (int ks = 0; ks < 2; ks++) {
            uint32_t bfr[4][4];
            #pragma unroll
            for (int nq = 0; nq < 4; nq++)
                ldsm4(bfr[nq], smem_u32(&Ksb[(nq * 16 + lmb_row) * 40 +
                                             ks * 16 + lmb_col8]));
            #pragma unroll
            for (int mi = 0; mi < 2; mi++)
                #pragma unroll
                for (int nq = 0; nq < 4; nq++) {
                    mma_f16(sc[mi][2 * nq],     qf[mi][ks], &bfr[nq][0]);
                    mma_f16(sc[mi][2 * nq + 1], qf[mi][ks], &bfr[nq][2]);
                }
        }

        // Online softmax (base-2): ex2.f16x2 straight to P; no scalar row-sum
        #pragma unroll
        for (int mi = 0; mi < 2; mi++) {
            const int rb = w * 32 + mi * 16 + r0;
            float mt0 = -1e30f, mt1 = -1e30f;
            #pragma unroll
            for (int ni = 0; ni < 8; ni++) {
                mt0 = fmaxf(mt0, fmaxf(sc[mi][ni][0], sc[mi][ni][1]));
                mt1 = fmaxf(mt1, fmaxf(sc[mi][ni][2], sc[mi][ni][3]));
            }
            #pragma unroll
            for (int off = 1; off < 4; off <<= 1) {
                mt0 = fmaxf(mt0, __shfl_xor_sync(0xffffffffu, mt0, off));
                mt1 = fmaxf(mt1, __shfl_xor_sync(0xffffffffu, mt1, off));
            }
            const float mn0 = fmaxf(m[mi][0], mt0);
            const float mn1 = fmaxf(m[mi][1], mt1);
            const float alpha0 = ex2(m[mi][0] - mn0);
            const float alpha1 = ex2(m[mi][1] - mn1);
            m[mi][0] = mn0; m[mi][1] = mn1;

            #pragma unroll
            for (int ni = 0; ni < 8; ni++) {
                const int col = ni * 8 + 2 * quad;
                *reinterpret_cast<uint32_t*>(&Ps[rb * 72 + col]) =
                    ex2h2(sc[mi][ni][0] - mn0, sc[mi][ni][1] - mn0);
                *reinterpret_cast<uint32_t*>(&Ps[(rb + 8) * 72 + col]) =
                    ex2h2(sc[mi][ni][2] - mn1, sc[mi][ni][3] - mn1);
            }
            #pragma unroll
            for (int ni = 0; ni < 4; ni++) {
                o[mi][ni][0] *= alpha0; o[mi][ni][1] *= alpha0;
                o[mi][ni][2] *= alpha1; o[mi][ni][3] *= alpha1;
            }
            oE[mi][0] *= alpha0; oE[mi][1] *= alpha0;
            oE[mi][2] *= alpha1; oE[mi][3] *= alpha1;
        }
        __syncwarp();   // P rows warp-private: order write -> ldmatrix read

        // O += P @ V ; l += P @ ones (constant B-fragment)
        #pragma unroll
        for (int ks = 0; ks < 4; ks++) {
            uint32_t a[2][4], b[2][4];
            #pragma unroll
            for (int mi = 0; mi < 2; mi++) {
                const int rb = w * 32 + mi * 16;
                ldsm4(a[mi], smem_u32(&Ps[(rb + lm_row) * 72 + ks * 16 + lm_col8]));
            }
            #pragma unroll
            for (int ni2 = 0; ni2 < 2; ni2++)
                ldsm4t(b[ni2], smem_u32(&Vsb[(ks * 16 + lm_row) * 40 +
                                             ni2 * 16 + lm_col8]));
            #pragma unroll
            for (int mi = 0; mi < 2; mi++) {
                #pragma unroll
                for (int ni2 = 0; ni2 < 2; ni2++) {
                    mma_f16(o[mi][2 * ni2],     a[mi], &b[ni2][0]);
                    mma_f16(o[mi][2 * ni2 + 1], a[mi], &b[ni2][2]);
                }
                mma_f16(oE[mi], a[mi], onesfrag);
            }
        }
        __syncthreads();   // stage s fully consumed before it is overwritten
    }

    #pragma unroll
    for (int mi = 0; mi < 2; mi++) {
        const float inv0 = 1.0f / oE[mi][0];
        const float inv1 = 1.0f / oE[mi][2];
        const int q = q0 + w * 32 + mi * 16 + r0;
        #pragma unroll
        for (int ni = 0; ni < 4; ni++) {
            const int d = ni * 8 + 2 * quad;
            *reinterpret_cast<__half2*>(&O[base + q * D_MODEL + d]) =
                __floats2half2_rn(o[mi][ni][0] * inv0, o[mi][ni][1] * inv0);
            *reinterpret_cast<__half2*>(&O[base + (q + 8) * D_MODEL + d]) =
                __floats2half2_rn(o[mi][ni][2] * inv1, o[mi][ni][3] * inv1);
        }
    }
}

// ---------------------------------------------------------------------------
// Launch
// ---------------------------------------------------------------------------
extern "C" void kernel_launch(void* const* d_in, const int* in_sizes, int n_in,
                              void* d_out, int out_size)
{
    const float* x    = (const float*)d_in[0];
    const float* ln1s = (const float*)d_in[1];
    const float* ln1b = (const float*)d_in[2];
    const float* wq   = (const float*)d_in[3];
    const float* bq   = (const float*)d_in[4];
    const float* wk   = (const float*)d_in[5];
    const float* bk   = (const float*)d_in[6];
    const float* wv   = (const float*)d_in[7];
    const float* bv   = (const float*)d_in[8];
    const float* wo   = (const float*)d_in[9];
    const float* bo   = (const float*)d_in[10];
    const float* ln2s = (const float*)d_in[11];
    const float* ln2b = (const float*)d_in[12];
    const float* w1   = (const float*)d_in[13];
    const float* b1   = (const float*)d_in[14];
    const float* w2   = (const float*)d_in[15];
    const float* b2   = (const float*)d_in[16];

    float* X = (float*)d_out;

    __half *normed, *q, *k, *v, *attn, *ffh;
    __half *wq16, *wk16, *wv16, *wo16, *w116, *w216;
    cudaGetSymbolAddress((void**)&normed, g_normed);
    cudaGetSymbolAddress((void**)&q,      g_q);
    cudaGetSymbolAddress((void**)&k,      g_k);
    cudaGetSymbolAddress((void**)&v,      g_v);
    cudaGetSymbolAddress((void**)&attn,   g_attn);
    cudaGetSymbolAddress((void**)&ffh,    g_ffh);
    cudaGetSymbolAddress((void**)&wq16,   g_wq16);
    cudaGetSymbolAddress((void**)&wk16,   g_wk16);
    cudaGetSymbolAddress((void**)&wv16,   g_wv16);
    cudaGetSymbolAddress((void**)&wo16,   g_wo16);
    cudaGetSymbolAddress((void**)&w116,   g_w116);
    cudaGetSymbolAddress((void**)&w216,   g_w216);

    cudaFuncSetAttribute(attn_kernel,
                         cudaFuncAttributeMaxDynamicSharedMemorySize, ATTN_SMEM_BYTES);

    cudaMemcpyAsync(X, x, (size_t)NTOK * D_MODEL * sizeof(float),
                    cudaMemcpyDeviceToDevice);

    cvt_all_kernel<<<(TOT4 + 255) / 256, 256>>>(wq, wk, wv, wo, w1, w2,
                                                wq16, wk16, wv16, wo16, w116, w216);

    const float qscale = 0.17677669529663687f * 1.4426950408889634f;  // /sqrt(32)*log2(e)

    const dim3 gemm_dd(D_MODEL / 64, NTOK / 64);      // (4, 128)
    const dim3 gemm_df(D_FF / 64,    NTOK / 64);      // (16, 128)
    const dim3 qkv_grid(D_MODEL / 64, NTOK / 64, 3);
    const dim3 attn_grid(SEQ / 128, N_HEADS, BATCH);  // (16, 8, 4)

    for (int ly = 0; ly < N_LAYERS; ly++) {
        const int wdd = ly * D_MODEL * D_MODEL;
        const int wdf = ly * D_MODEL * D_FF;

        ln_kernel<<<NTOK / 8, 256>>>(X, ln1s + ly * D_MODEL, ln1b + ly * D_MODEL, normed);

        qkv16_kernel<<<qkv_grid, 128, GEMM_SMEM_BYTES>>>(
            normed, wq16 + wdd, wk16 + wdd, wv16 + wdd,
            bq + ly * D_MODEL, bk + ly * D_MODEL, bv + ly * D_MODEL,
            q, k, v, qscale);

        attn_kernel<<<attn_grid, 128, ATTN_SMEM_BYTES>>>(q, k, v, attn);

        gemm16_kernel<2><<<gemm_dd, 128, GEMM_SMEM_BYTES>>>(
            attn, wo16 + wdd, bo + ly * D_MODEL, (void*)X, D_MODEL, D_MODEL, 1.0f);

        ln_kernel<<<NTOK / 8, 256>>>(X, ln2s + ly * D_MODEL, ln2b + ly * D_MODEL, normed);

        gemm16_kernel<1><<<gemm_df, 128, GEMM_SMEM_BYTES>>>(
            normed, w116 + wdf, b1 + ly * D_FF, (void*)ffh, D_MODEL, D_FF, 1.0f);

        gemm16_kernel<2><<<gemm_dd, 128, GEMM_SMEM_BYTES>>>(
            ffh, w216 + wdf, b2 + ly * D_MODEL, (void*)X, D_FF, D_MODEL, 1.0f);
    }
}

// round 9
// speedup vs baseline: 1.8407x; 1.0152x over previous
#include <cuda_runtime.h>
#include <cuda_fp16.h>
#include <math.h>
#include <stdint.h>

#define D_MODEL   256
#define N_LAYERS  6
#define N_HEADS   8
#define D_FF      1024
#define HEAD_DIM  32
#define BATCH     4
#define SEQ       2048
#define NTOK      (BATCH * SEQ)   // 8192

// ---------------------------------------------------------------------------
// Scratch (fp16 activations + fp16 weight shadows)
// ---------------------------------------------------------------------------
__device__ __align__(16) __half g_normed[NTOK * D_MODEL];
__device__ __align__(16) __half g_q[NTOK * D_MODEL];
__device__ __align__(16) __half g_k[NTOK * D_MODEL];
__device__ __align__(16) __half g_v[NTOK * D_MODEL];
__device__ __align__(16) __half g_attn[NTOK * D_MODEL];
__device__ __align__(16) __half g_ffh[NTOK * D_FF];

__device__ __align__(16) __half g_wq16[N_LAYERS * D_MODEL * D_MODEL];
__device__ __align__(16) __half g_wk16[N_LAYERS * D_MODEL * D_MODEL];
__device__ __align__(16) __half g_wv16[N_LAYERS * D_MODEL * D_MODEL];
__device__ __align__(16) __half g_wo16[N_LAYERS * D_MODEL * D_MODEL];
__device__ __align__(16) __half g_w116[N_LAYERS * D_MODEL * D_FF];
__device__ __align__(16) __half g_w216[N_LAYERS * D_FF * D_MODEL];

// ---------------------------------------------------------------------------
// Helpers
// ---------------------------------------------------------------------------
__device__ __forceinline__ uint32_t smem_u32(const void* p) {
    return (uint32_t)__cvta_generic_to_shared(p);
}
#define CPA16(dst_u32, src_ptr) \
    asm volatile("cp.async.cg.shared.global [%0], [%1], 16;\n" :: "r"(dst_u32), "l"(src_ptr))
#define CPA_COMMIT() asm volatile("cp.async.commit_group;\n" ::)
#define CPA_WAIT3()  asm volatile("cp.async.wait_group 3;\n" ::)
#define CPA_WAIT2()  asm volatile("cp.async.wait_group 2;\n" ::)
#define CPA_WAIT1()  asm volatile("cp.async.wait_group 1;\n" ::)
#define CPA_WAIT0()  asm volatile("cp.async.wait_group 0;\n" ::)

// HMMA m16n8k16 fp16 -> fp32 accum
__device__ __forceinline__ void mma_f16(float* c, const uint32_t* a, const uint32_t* b) {
    asm volatile(
        "mma.sync.aligned.m16n8k16.row.col.f32.f16.f16.f32 "
        "{%0,%1,%2,%3},{%4,%5,%6,%7},{%8,%9},{%0,%1,%2,%3};\n"
        : "+f"(c[0]), "+f"(c[1]), "+f"(c[2]), "+f"(c[3])
        : "r"(a[0]), "r"(a[1]), "r"(a[2]), "r"(a[3]),
          "r"(b[0]), "r"(b[1]));
}

__device__ __forceinline__ void ldsm4(uint32_t* r, uint32_t byte_addr) {
    asm volatile("ldmatrix.sync.aligned.m8n8.x4.shared.b16 {%0,%1,%2,%3}, [%4];\n"
        : "=r"(r[0]), "=r"(r[1]), "=r"(r[2]), "=r"(r[3]) : "r"(byte_addr));
}
__device__ __forceinline__ void ldsm4t(uint32_t* r, uint32_t byte_addr) {
    asm volatile("ldmatrix.sync.aligned.m8n8.x4.trans.shared.b16 {%0,%1,%2,%3}, [%4];\n"
        : "=r"(r[0]), "=r"(r[1]), "=r"(r[2]), "=r"(r[3]) : "r"(byte_addr));
}

__device__ __forceinline__ float ex2(float x) {
    float y;
    asm("ex2.approx.f32 %0, %1;" : "=f"(y) : "f"(x));
    return y;
}
// pack two floats to half2 then 2^x elementwise -> packed half2 (A-frag ready)
__device__ __forceinline__ uint32_t ex2h2(float a, float b) {
    __half2 h = __floats2half2_rn(a, b);
    uint32_t hu = *reinterpret_cast<uint32_t*>(&h);
    uint32_t r;
    asm("ex2.approx.f16x2 %0, %1;" : "=r"(r) : "r"(hu));
    return r;
}

// ---------------------------------------------------------------------------
// Merged fp32 -> fp16 weight conversion
// ---------------------------------------------------------------------------
#define DD4 (N_LAYERS * D_MODEL * D_MODEL / 4)
#define DF4 (N_LAYERS * D_MODEL * D_FF / 4)
#define TOT4 (4 * DD4 + 2 * DF4)

__global__ void __launch_bounds__(256) cvt_all_kernel(
    const float* __restrict__ wq, const float* __restrict__ wk,
    const float* __restrict__ wv, const float* __restrict__ wo,
    const float* __restrict__ w1, const float* __restrict__ w2,
    __half* __restrict__ wq16, __half* __restrict__ wk16,
    __half* __restrict__ wv16, __half* __restrict__ wo16,
    __half* __restrict__ w116, __half* __restrict__ w216)
{
    const int i = blockIdx.x * blockDim.x + threadIdx.x;
    if (i >= TOT4) return;
    const float* src; __half* dst; int off;
    if (i < DD4)          { src = wq; dst = wq16; off = i; }
    else if (i < 2 * DD4) { src = wk; dst = wk16; off = i - DD4; }
    else if (i < 3 * DD4) { src = wv; dst = wv16; off = i - 2 * DD4; }
    else if (i < 4 * DD4) { src = wo; dst = wo16; off = i - 3 * DD4; }
    else if (i < 4 * DD4 + DF4) { src = w1; dst = w116; off = i - 4 * DD4; }
    else                  { src = w2; dst = w216; off = i - 4 * DD4 - DF4; }
    float4 v = reinterpret_cast<const float4*>(src)[off];
    __half2 h0 = __floats2half2_rn(v.x, v.y);
    __half2 h1 = __floats2half2_rn(v.z, v.w);
    reinterpret_cast<__half2*>(dst)[2 * off]     = h0;
    reinterpret_cast<__half2*>(dst)[2 * off + 1] = h1;
}

// ---------------------------------------------------------------------------
// LayerNorm: warp per row, float4 loads, fp16 out.
// ---------------------------------------------------------------------------
__global__ void __launch_bounds__(256) ln_kernel(
    const float* __restrict__ X, const float* __restrict__ S,
    const float* __restrict__ Bb, __half* __restrict__ Y)
{
    const int row  = blockIdx.x * 8 + (threadIdx.x >> 5);
    const int lane = threadIdx.x & 31;
    const int c0   = lane * 8;

    const float4 a = *reinterpret_cast<const float4*>(&X[row * D_MODEL + c0]);
    const float4 b = *reinterpret_cast<const float4*>(&X[row * D_MODEL + c0 + 4]);

    float s1 = a.x + a.y + a.z + a.w + b.x + b.y + b.z + b.w;
    float s2 = a.x * a.x + a.y * a.y + a.z * a.z + a.w * a.w
             + b.x * b.x + b.y * b.y + b.z * b.z + b.w * b.w;
    #pragma unroll
    for (int off = 16; off > 0; off >>= 1) {
        s1 += __shfl_xor_sync(0xffffffffu, s1, off);
        s2 += __shfl_xor_sync(0xffffffffu, s2, off);
    }
    const float mu  = s1 * (1.0f / D_MODEL);
    const float var = s2 * (1.0f / D_MODEL) - mu * mu;
    const float inv = rsqrtf(var + 1e-5f);

    const float4 sa = *reinterpret_cast<const float4*>(&S[c0]);
    const float4 sb = *reinterpret_cast<const float4*>(&S[c0 + 4]);
    const float4 ba = *reinterpret_cast<const float4*>(&Bb[c0]);
    const float4 bb = *reinterpret_cast<const float4*>(&Bb[c0 + 4]);

    __half2 h[4];
    h[0] = __floats2half2_rn((a.x - mu) * inv * sa.x + ba.x, (a.y - mu) * inv * sa.y + ba.y);
    h[1] = __floats2half2_rn((a.z - mu) * inv * sa.z + ba.z, (a.w - mu) * inv * sa.w + ba.w);
    h[2] = __floats2half2_rn((b.x - mu) * inv * sb.x + bb.x, (b.y - mu) * inv * sb.y + bb.y);
    h[3] = __floats2half2_rn((b.z - mu) * inv * sb.z + bb.z, (b.w - mu) * inv * sb.w + bb.w);
    *reinterpret_cast<uint4*>(&Y[row * D_MODEL + c0]) = *reinterpret_cast<uint4*>(h);
}

// ---------------------------------------------------------------------------
// fp16 GEMM (unchanged from round 8)
// ---------------------------------------------------------------------------
#define GEMM_SMEM_BYTES (3 * (64 * 40 + 32 * 72) * 2)

template <int MODE>
__device__ __forceinline__ void gemm16_body(
    const __half* __restrict__ A, const __half* __restrict__ W,
    const float* __restrict__ bias, void* Cv, int K, int M, float oscale)
{
    extern __shared__ __align__(16) __half smexh[];
    __half* As = smexh;
    __half* Ws = smexh + 3 * 64 * 40;

    const int tid  = threadIdx.x;
    const int lane = tid & 31;
    const int wid  = tid >> 5;
    const int warp_m = wid >> 1;
    const int warp_n = wid & 1;
    const int r0   = lane >> 2;
    const int quad = lane & 3;
    const int row0 = blockIdx.y * 64;
    const int col0 = blockIdx.x * 64;

    const int lm_row  = lane & 15;
    const int lm_col8 = (lane >> 4) << 3;

    float acc[2][4][4] = {};

    auto load_stage = [&](int k0, int s) {
        __half* Asb = As + s * (64 * 40);
        #pragma unroll
        for (int i = 0; i < 2; i++) {
            int e = tid + i * 128;
            int r = e >> 2, c8 = e & 3;
            CPA16(smem_u32(&Asb[r * 40 + c8 * 8]),
                  A + (size_t)(row0 + r) * K + k0 + c8 * 8);
        }
        __half* Wsb = Ws + s * (32 * 72);
        #pragma unroll
        for (int i = 0; i < 2; i++) {
            int e = tid + i * 128;
            int r = e >> 3, c8 = e & 7;
            CPA16(smem_u32(&Wsb[r * 72 + c8 * 8]),
                  W + (size_t)(k0 + r) * M + col0 + c8 * 8);
        }
        CPA_COMMIT();
    };

    const int nk = K >> 5;
    load_stage(0, 0);
    load_stage(32, 1);

    for (int it = 0; it < nk; ++it) {
        const int s = it % 3;
        if (it + 2 < nk)      { load_stage((it + 2) * 32, (it + 2) % 3); CPA_WAIT2(); }
        else if (it + 1 < nk) { CPA_WAIT1(); }
        else                  { CPA_WAIT0(); }
        __syncthreads();

        const __half* Asb = As + s * (64 * 40);
        const __half* Wsb = Ws + s * (32 * 72);

        #pragma unroll
        for (int ks = 0; ks < 2; ks++) {
            uint32_t a[2][4], b[2][4];
            #pragma unroll
            for (int mi = 0; mi < 2; mi++) {
                const int rb = warp_m * 32 + mi * 16;
                ldsm4(a[mi], smem_u32(&Asb[(rb + lm_row) * 40 + ks * 16 + lm_col8]));
            }
            #pragma unroll
            for (int ni2 = 0; ni2 < 2; ni2++) {
                ldsm4t(b[ni2], smem_u32(&Wsb[(ks * 16 + lm_row) * 72 +
                                             warp_n * 32 + ni2 * 16 + lm_col8]));
            }
            #pragma unroll
            for (int mi = 0; mi < 2; mi++)
                #pragma unroll
                for (int ni2 = 0; ni2 < 2; ni2++) {
                    mma_f16(acc[mi][2 * ni2],     a[mi], &b[ni2][0]);
                    mma_f16(acc[mi][2 * ni2 + 1], a[mi], &b[ni2][2]);
                }
        }
        __syncthreads();
    }

    #pragma unroll
    for (int mi = 0; mi < 2; mi++) {
        #pragma unroll
        for (int ni = 0; ni < 4; ni++) {
            const int r = row0 + warp_m * 32 + mi * 16 + r0;
            const int c = col0 + warp_n * 32 + ni * 8 + 2 * quad;
            const float bx = bias[c], by = bias[c + 1];
            float v0 = acc[mi][ni][0] + bx;
            float v1 = acc[mi][ni][1] + by;
            float v2 = acc[mi][ni][2] + bx;
            float v3 = acc[mi][ni][3] + by;
            if (MODE == 1) {
                v0 = 0.5f * v0 * (1.0f + erff(v0 * 0.70710678118654752f));
                v1 = 0.5f * v1 * (1.0f + erff(v1 * 0.70710678118654752f));
                v2 = 0.5f * v2 * (1.0f + erff(v2 * 0.70710678118654752f));
                v3 = 0.5f * v3 * (1.0f + erff(v3 * 0.70710678118654752f));
            }
            if (MODE == 2) {
                float* Cf = (float*)Cv;
                float2 e0 = *reinterpret_cast<const float2*>(&Cf[(size_t)r * M + c]);
                float2 e1 = *reinterpret_cast<const float2*>(&Cf[(size_t)(r + 8) * M + c]);
                *reinterpret_cast<float2*>(&Cf[(size_t)r * M + c]) =
                    make_float2(v0 + e0.x, v1 + e0.y);
                *reinterpret_cast<float2*>(&Cf[(size_t)(r + 8) * M + c]) =
                    make_float2(v2 + e1.x, v3 + e1.y);
            } else {
                __half* Ch = (__half*)Cv;
                *reinterpret_cast<__half2*>(&Ch[(size_t)r * M + c]) =
                    __floats2half2_rn(v0 * oscale, v1 * oscale);
                *reinterpret_cast<__half2*>(&Ch[(size_t)(r + 8) * M + c]) =
                    __floats2half2_rn(v2 * oscale, v3 * oscale);
            }
        }
    }
}

template <int MODE>
__global__ void __launch_bounds__(128) gemm16_kernel(
    const __half* __restrict__ A, const __half* __restrict__ W,
    const float* __restrict__ bias, void* Cv, int K, int M, float oscale)
{
    gemm16_body<MODE>(A, W, bias, Cv, K, M, oscale);
}

__global__ void __launch_bounds__(128) qkv16_kernel(
    const __half* __restrict__ A,
    const __half* __restrict__ wq, const __half* __restrict__ wk, const __half* __restrict__ wv,
    const float* __restrict__ bq, const float* __restrict__ bk, const float* __restrict__ bv,
    __half* __restrict__ q, __half* __restrict__ k, __half* __restrict__ v, float qscale)
{
    const __half* W; const float* B; __half* C; float os;
    if (blockIdx.z == 0)      { W = wq; B = bq; C = q; os = qscale; }
    else if (blockIdx.z == 1) { W = wk; B = bk; C = k; os = 1.0f; }
    else                      { W = wv; B = bv; C = v; os = 1.0f; }
    gemm16_body<0>(A, W, B, (void*)C, D_MODEL, D_MODEL, os);
}

// ---------------------------------------------------------------------------
// Flash attention fp16, REGISTER-RESIDENT P:
// S-accumulator fragments convert (ex2.f16x2) directly into PV A-fragments.
// No P smem, no P ldmatrix, 4-stage KV pipeline, ONE barrier per iteration.
// smem: Q[128*40] + 4*(K[64*40]+V[64*40]) = 51200 B -> 4 CTA/SM target.
// ---------------------------------------------------------------------------
#define ATTN_SMEM_BYTES ((128 * 40 + 4 * 2 * (64 * 40)) * 2)

__global__ void __launch_bounds__(128, 4) attn_kernel(
    const __half* __restrict__ Q, const __half* __restrict__ K,
    const __half* __restrict__ V, __half* __restrict__ O)
{
    extern __shared__ __align__(16) __half smexh[];
    __half* Qs = smexh;                    // 128*40
    __half* Ks = Qs + 128 * 40;            // [4][64*40]
    __half* Vs = Ks + 4 * 64 * 40;         // [4][64*40]

    const int tid  = threadIdx.x;
    const int lane = tid & 31;
    const int w    = tid >> 5;
    const int r0   = lane >> 2;
    const int quad = lane & 3;
    const int q0   = blockIdx.x * 128;
    const int h    = blockIdx.y;
    const int b    = blockIdx.z;
    const int base = (b * SEQ) * D_MODEL + h * HEAD_DIM;

    const int lm_row  = lane & 15;
    const int lm_col8 = (lane >> 4) << 3;
    const int lmb_row  = (lane & 7) + ((lane >> 4) << 3);
    const int lmb_col8 = (((lane >> 3) & 1) << 3);

    // Q load (its own commit group)
    {
        #pragma unroll
        for (int i = 0; i < 4; i++) {
            int e = tid + i * 128;
            int r = e >> 2, c8 = e & 3;
            CPA16(smem_u32(&Qs[r * 40 + c8 * 8]),
                  &Q[base + (q0 + r) * D_MODEL + c8 * 8]);
        }
        CPA_COMMIT();
    }

    auto load_kv = [&](int kt, int s) {
        __half* Ksb = Ks + s * (64 * 40);
        __half* Vsb = Vs + s * (64 * 40);
        #pragma unroll
        for (int i = 0; i < 2; i++) {
            const int e = tid + i * 128;
            const int r = e >> 2, c8 = e & 3;
            CPA16(smem_u32(&Ksb[r * 40 + c8 * 8]), &K[base + (kt + r) * D_MODEL + c8 * 8]);
            CPA16(smem_u32(&Vsb[r * 40 + c8 * 8]), &V[base + (kt + r) * D_MODEL + c8 * 8]);
        }
        CPA_COMMIT();
    };

    load_kv(0, 0);
    load_kv(64, 1);
    load_kv(128, 2);

    // Wait for Q (3 KV groups may stay pending), hoist Q fragments
    CPA_WAIT3();
    __syncthreads();
    uint32_t qf[2][2][4];
    #pragma unroll
    for (int mi = 0; mi < 2; mi++) {
        const int rb = w * 32 + mi * 16;
        #pragma unroll
        for (int ks = 0; ks < 2; ks++)
            ldsm4(qf[mi][ks], smem_u32(&Qs[(rb + lm_row) * 40 + ks * 16 + lm_col8]));
    }

    float m[2][2], o[2][4][4] = {}, oE[2][4] = {};
    #pragma unroll
    for (int mi = 0; mi < 2; mi++) { m[mi][0] = m[mi][1] = -1e30f; }

    const uint32_t onesfrag[2] = {0x3C003C00u, 0x3C003C00u};

    const int NIT = SEQ / 64;
    for (int it = 0; it < NIT; ++it) {
        const int s = it & 3;
        // wait ladder: stage `it` complete
        if (it + 2 < NIT)      { CPA_WAIT2(); }
        else if (it + 1 < NIT) { CPA_WAIT1(); }
        else                   { CPA_WAIT0(); }
        __syncthreads();   // single barrier: data visible AND all warps done with slot (it+3)&3
        if (it + 3 < NIT) load_kv((it + 3) * 64, (it + 3) & 3);

        const __half* Ksb = Ks + s * (64 * 40);
        const __half* Vsb = Vs + s * (64 * 40);

        // S = Q K^T (log2-domain scores via pre-scaled Q)
        float sc[2][8][4] = {};
        #pragma unroll
        for (int ks = 0; ks < 2; ks++) {
            uint32_t bfr[4][4];
            #pragma unroll
            for (int nq = 0; nq < 4; nq++)
                ldsm4(bfr[nq], smem_u32(&Ksb[(nq * 16 + lmb_row) * 40 +
                                             ks * 16 + lmb_col8]));
            #pragma unroll
            for (int mi = 0; mi < 2; mi++)
                #pragma unroll
                for (int nq = 0; nq < 4; nq++) {
                    mma_f16(sc[mi][2 * nq],     qf[mi][ks], &bfr[nq][0]);
                    mma_f16(sc[mi][2 * nq + 1], qf[mi][ks], &bfr[nq][2]);
                }
        }

        // Online softmax: sc -> register A-fragments pa (no smem round-trip)
        uint32_t pa[2][4][4];
        #pragma unroll
        for (int mi = 0; mi < 2; mi++) {
            float mt0 = -1e30f, mt1 = -1e30f;
            #pragma unroll
            for (int ni = 0; ni < 8; ni++) {
                mt0 = fmaxf(mt0, fmaxf(sc[mi][ni][0], sc[mi][ni][1]));
                mt1 = fmaxf(mt1, fmaxf(sc[mi][ni][2], sc[mi][ni][3]));
            }
            #pragma unroll
            for (int off = 1; off < 4; off <<= 1) {
                mt0 = fmaxf(mt0, __shfl_xor_sync(0xffffffffu, mt0, off));
                mt1 = fmaxf(mt1, __shfl_xor_sync(0xffffffffu, mt1, off));
            }
            const float mn0 = fmaxf(m[mi][0], mt0);
            const float mn1 = fmaxf(m[mi][1], mt1);
            const float alpha0 = ex2(m[mi][0] - mn0);
            const float alpha1 = ex2(m[mi][1] - mn1);
            m[mi][0] = mn0; m[mi][1] = mn1;

            #pragma unroll
            for (int ks = 0; ks < 4; ks++) {
                pa[mi][ks][0] = ex2h2(sc[mi][2 * ks][0] - mn0,     sc[mi][2 * ks][1] - mn0);
                pa[mi][ks][1] = ex2h2(sc[mi][2 * ks][2] - mn1,     sc[mi][2 * ks][3] - mn1);
                pa[mi][ks][2] = ex2h2(sc[mi][2 * ks + 1][0] - mn0, sc[mi][2 * ks + 1][1] - mn0);
                pa[mi][ks][3] = ex2h2(sc[mi][2 * ks + 1][2] - mn1, sc[mi][2 * ks + 1][3] - mn1);
            }
            #pragma unroll
            for (int ni = 0; ni < 4; ni++) {
                o[mi][ni][0] *= alpha0; o[mi][ni][1] *= alpha0;
                o[mi][ni][2] *= alpha1; o[mi][ni][3] *= alpha1;
            }
            oE[mi][0] *= alpha0; oE[mi][1] *= alpha0;
            oE[mi][2] *= alpha1; oE[mi][3] *= alpha1;
        }

        // O += P @ V ; l += P @ ones   (A-frags register-resident)
        #pragma unroll
        for (int ks = 0; ks < 4; ks++) {
            uint32_t b[2][4];
            #pragma unroll
            for (int ni2 = 0; ni2 < 2; ni2++)
                ldsm4t(b[ni2], smem_u32(&Vsb[(ks * 16 + lm_row) * 40 +
                                             ni2 * 16 + lm_col8]));
            #pragma unroll
            for (int mi = 0; mi < 2; mi++) {
                #pragma unroll
                for (int ni2 = 0; ni2 < 2; ni2++) {
                    mma_f16(o[mi][2 * ni2],     pa[mi][ks], &b[ni2][0]);
                    mma_f16(o[mi][2 * ni2 + 1], pa[mi][ks], &b[ni2][2]);
                }
                mma_f16(oE[mi], pa[mi][ks], onesfrag);
            }
        }
    }

    #pragma unroll
    for (int mi = 0; mi < 2; mi++) {
        const float inv0 = 1.0f / oE[mi][0];
        const float inv1 = 1.0f / oE[mi][2];
        const int q = q0 + w * 32 + mi * 16 + r0;
        #pragma unroll
        for (int ni = 0; ni < 4; ni++) {
            const int d = ni * 8 + 2 * quad;
            *reinterpret_cast<__half2*>(&O[base + q * D_MODEL + d]) =
                __floats2half2_rn(o[mi][ni][0] * inv0, o[mi][ni][1] * inv0);
            *reinterpret_cast<__half2*>(&O[base + (q + 8) * D_MODEL + d]) =
                __floats2half2_rn(o[mi][ni][2] * inv1, o[mi][ni][3] * inv1);
        }
    }
}

// ---------------------------------------------------------------------------
// Launch
// ---------------------------------------------------------------------------
extern "C" void kernel_launch(void* const* d_in, const int* in_sizes, int n_in,
                              void* d_out, int out_size)
{
    const float* x    = (const float*)d_in[0];
    const float* ln1s = (const float*)d_in[1];
    const float* ln1b = (const float*)d_in[2];
    const float* wq   = (const float*)d_in[3];
    const float* bq   = (const float*)d_in[4];
    const float* wk   = (const float*)d_in[5];
    const float* bk   = (const float*)d_in[6];
    const float* wv   = (const float*)d_in[7];
    const float* bv   = (const float*)d_in[8];
    const float* wo   = (const float*)d_in[9];
    const float* bo   = (const float*)d_in[10];
    const float* ln2s = (const float*)d_in[11];
    const float* ln2b = (const float*)d_in[12];
    const float* w1   = (const float*)d_in[13];
    const float* b1   = (const float*)d_in[14];
    const float* w2   = (const float*)d_in[15];
    const float* b2   = (const float*)d_in[16];

    float* X = (float*)d_out;

    __half *normed, *q, *k, *v, *attn, *ffh;
    __half *wq16, *wk16, *wv16, *wo16, *w116, *w216;
    cudaGetSymbolAddress((void**)&normed, g_normed);
    cudaGetSymbolAddress((void**)&q,      g_q);
    cudaGetSymbolAddress((void**)&k,      g_k);
    cudaGetSymbolAddress((void**)&v,      g_v);
    cudaGetSymbolAddress((void**)&attn,   g_attn);
    cudaGetSymbolAddress((void**)&ffh,    g_ffh);
    cudaGetSymbolAddress((void**)&wq16,   g_wq16);
    cudaGetSymbolAddress((void**)&wk16,   g_wk16);
    cudaGetSymbolAddress((void**)&wv16,   g_wv16);
    cudaGetSymbolAddress((void**)&wo16,   g_wo16);
    cudaGetSymbolAddress((void**)&w116,   g_w116);
    cudaGetSymbolAddress((void**)&w216,   g_w216);

    cudaFuncSetAttribute(attn_kernel,
                         cudaFuncAttributeMaxDynamicSharedMemorySize, ATTN_SMEM_BYTES);

    cudaMemcpyAsync(X, x, (size_t)NTOK * D_MODEL * sizeof(float),
                    cudaMemcpyDeviceToDevice);

    cvt_all_kernel<<<(TOT4 + 255) / 256, 256>>>(wq, wk, wv, wo, w1, w2,
                                                wq16, wk16, wv16, wo16, w116, w216);

    const float qscale = 0.17677669529663687f * 1.4426950408889634f;

    const dim3 gemm_dd(D_MODEL / 64, NTOK / 64);
    const dim3 gemm_df(D_FF / 64,    NTOK / 64);
    const dim3 qkv_grid(D_MODEL / 64, NTOK / 64, 3);
    const dim3 attn_grid(SEQ / 128, N_HEADS, BATCH);

    for (int ly = 0; ly < N_LAYERS; ly++) {
        const int wdd = ly * D_MODEL * D_MODEL;
        const int wdf = ly * D_MODEL * D_FF;

        ln_kernel<<<NTOK / 8, 256>>>(X, ln1s + ly * D_MODEL, ln1b + ly * D_MODEL, normed);

        qkv16_kernel<<<qkv_grid, 128, GEMM_SMEM_BYTES>>>(
            normed, wq16 + wdd, wk16 + wdd, wv16 + wdd,
            bq + ly * D_MODEL, bk + ly * D_MODEL, bv + ly * D_MODEL,
            q, k, v, qscale);

        attn_kernel<<<attn_grid, 128, ATTN_SMEM_BYTES>>>(q, k, v, attn);

        gemm16_kernel<2><<<gemm_dd, 128, GEMM_SMEM_BYTES>>>(
            attn, wo16 + wdd, bo + ly * D_MODEL, (void*)X, D_MODEL, D_MODEL, 1.0f);

        ln_kernel<<<NTOK / 8, 256>>>(X, ln2s + ly * D_MODEL, ln2b + ly * D_MODEL, normed);

        gemm16_kernel<1><<<gemm_df, 128, GEMM_SMEM_BYTES>>>(
            normed, w116 + wdf, b1 + ly * D_FF, (void*)ffh, D_MODEL, D_FF, 1.0f);

        gemm16_kernel<2><<<gemm_dd, 128, GEMM_SMEM_BYTES>>>(
            ffh, w216 + wdf, b2 + ly * D_MODEL, (void*)X, D_FF, D_MODEL, 1.0f);
    }
}

// round 10
// speedup vs baseline: 1.9197x; 1.0430x over previous
#include <cuda_runtime.h>
#include <cuda_fp16.h>
#include <math.h>
#include <stdint.h>

#define D_MODEL   256
#define N_LAYERS  6
#define N_HEADS   8
#define D_FF      1024
#define HEAD_DIM  32
#define BATCH     4
#define SEQ       2048
#define NTOK      (BATCH * SEQ)   // 8192

// ---------------------------------------------------------------------------
// Scratch (fp16 activations + fp16 weight shadows)
// ---------------------------------------------------------------------------
__device__ __align__(16) __half g_normed[NTOK * D_MODEL];
__device__ __align__(16) __half g_q[NTOK * D_MODEL];
__device__ __align__(16) __half g_k[NTOK * D_MODEL];
__device__ __align__(16) __half g_v[NTOK * D_MODEL];
__device__ __align__(16) __half g_attn[NTOK * D_MODEL];
__device__ __align__(16) __half g_ffh[NTOK * D_FF];

__device__ __align__(16) __half g_wq16[N_LAYERS * D_MODEL * D_MODEL];
__device__ __align__(16) __half g_wk16[N_LAYERS * D_MODEL * D_MODEL];
__device__ __align__(16) __half g_wv16[N_LAYERS * D_MODEL * D_MODEL];
__device__ __align__(16) __half g_wo16[N_LAYERS * D_MODEL * D_MODEL];
__device__ __align__(16) __half g_w116[N_LAYERS * D_MODEL * D_FF];
__device__ __align__(16) __half g_w216[N_LAYERS * D_FF * D_MODEL];

// ---------------------------------------------------------------------------
// Helpers
// ---------------------------------------------------------------------------
__device__ __forceinline__ uint32_t smem_u32(const void* p) {
    return (uint32_t)__cvta_generic_to_shared(p);
}
#define CPA16(dst_u32, src_ptr) \
    asm volatile("cp.async.cg.shared.global [%0], [%1], 16;\n" :: "r"(dst_u32), "l"(src_ptr))
#define CPA_COMMIT() asm volatile("cp.async.commit_group;\n" ::)
#define CPA_WAIT3()  asm volatile("cp.async.wait_group 3;\n" ::)
#define CPA_WAIT2()  asm volatile("cp.async.wait_group 2;\n" ::)
#define CPA_WAIT1()  asm volatile("cp.async.wait_group 1;\n" ::)
#define CPA_WAIT0()  asm volatile("cp.async.wait_group 0;\n" ::)

// HMMA m16n8k16 fp16 -> fp32 accum
__device__ __forceinline__ void mma_f16(float* c, const uint32_t* a, const uint32_t* b) {
    asm volatile(
        "mma.sync.aligned.m16n8k16.row.col.f32.f16.f16.f32 "
        "{%0,%1,%2,%3},{%4,%5,%6,%7},{%8,%9},{%0,%1,%2,%3};\n"
        : "+f"(c[0]), "+f"(c[1]), "+f"(c[2]), "+f"(c[3])
        : "r"(a[0]), "r"(a[1]), "r"(a[2]), "r"(a[3]),
          "r"(b[0]), "r"(b[1]));
}

__device__ __forceinline__ void ldsm4(uint32_t* r, uint32_t byte_addr) {
    asm volatile("ldmatrix.sync.aligned.m8n8.x4.shared.b16 {%0,%1,%2,%3}, [%4];\n"
        : "=r"(r[0]), "=r"(r[1]), "=r"(r[2]), "=r"(r[3]) : "r"(byte_addr));
}
__device__ __forceinline__ void ldsm4t(uint32_t* r, uint32_t byte_addr) {
    asm volatile("ldmatrix.sync.aligned.m8n8.x4.trans.shared.b16 {%0,%1,%2,%3}, [%4];\n"
        : "=r"(r[0]), "=r"(r[1]), "=r"(r[2]), "=r"(r[3]) : "r"(byte_addr));
}

__device__ __forceinline__ float ex2(float x) {
    float y;
    asm("ex2.approx.f32 %0, %1;" : "=f"(y) : "f"(x));
    return y;
}
// packed-half2 primitives for softmax
__device__ __forceinline__ uint32_t f22h2(float lo, float hi) {
    __half2 h = __floats2half2_rn(lo, hi);
    return *reinterpret_cast<uint32_t*>(&h);
}
__device__ __forceinline__ uint32_t hmax2u(uint32_t a, uint32_t b) {
    uint32_t d;
    asm("max.f16x2 %0, %1, %2;" : "=r"(d) : "r"(a), "r"(b));
    return d;
}
__device__ __forceinline__ uint32_t hsub2u(uint32_t a, uint32_t b) {
    uint32_t d;
    asm("sub.f16x2 %0, %1, %2;" : "=r"(d) : "r"(a), "r"(b));
    return d;
}
__device__ __forceinline__ uint32_t hex2u(uint32_t a) {
    uint32_t d;
    asm("ex2.approx.f16x2 %0, %1;" : "=r"(d) : "r"(a));
    return d;
}

// ---------------------------------------------------------------------------
// Merged fp32 -> fp16 weight conversion
// ---------------------------------------------------------------------------
#define DD4 (N_LAYERS * D_MODEL * D_MODEL / 4)
#define DF4 (N_LAYERS * D_MODEL * D_FF / 4)
#define TOT4 (4 * DD4 + 2 * DF4)

__global__ void __launch_bounds__(256) cvt_all_kernel(
    const float* __restrict__ wq, const float* __restrict__ wk,
    const float* __restrict__ wv, const float* __restrict__ wo,
    const float* __restrict__ w1, const float* __restrict__ w2,
    __half* __restrict__ wq16, __half* __restrict__ wk16,
    __half* __restrict__ wv16, __half* __restrict__ wo16,
    __half* __restrict__ w116, __half* __restrict__ w216)
{
    const int i = blockIdx.x * blockDim.x + threadIdx.x;
    if (i >= TOT4) return;
    const float* src; __half* dst; int off;
    if (i < DD4)          { src = wq; dst = wq16; off = i; }
    else if (i < 2 * DD4) { src = wk; dst = wk16; off = i - DD4; }
    else if (i < 3 * DD4) { src = wv; dst = wv16; off = i - 2 * DD4; }
    else if (i < 4 * DD4) { src = wo; dst = wo16; off = i - 3 * DD4; }
    else if (i < 4 * DD4 + DF4) { src = w1; dst = w116; off = i - 4 * DD4; }
    else                  { src = w2; dst = w216; off = i - 4 * DD4 - DF4; }
    float4 v = reinterpret_cast<const float4*>(src)[off];
    __half2 h0 = __floats2half2_rn(v.x, v.y);
    __half2 h1 = __floats2half2_rn(v.z, v.w);
    reinterpret_cast<__half2*>(dst)[2 * off]     = h0;
    reinterpret_cast<__half2*>(dst)[2 * off + 1] = h1;
}

// ---------------------------------------------------------------------------
// LayerNorm: warp per row, float4 loads, fp16 out.
// ---------------------------------------------------------------------------
__global__ void __launch_bounds__(256) ln_kernel(
    const float* __restrict__ X, const float* __restrict__ S,
    const float* __restrict__ Bb, __half* __restrict__ Y)
{
    const int row  = blockIdx.x * 8 + (threadIdx.x >> 5);
    const int lane = threadIdx.x & 31;
    const int c0   = lane * 8;

    const float4 a = *reinterpret_cast<const float4*>(&X[row * D_MODEL + c0]);
    const float4 b = *reinterpret_cast<const float4*>(&X[row * D_MODEL + c0 + 4]);

    float s1 = a.x + a.y + a.z + a.w + b.x + b.y + b.z + b.w;
    float s2 = a.x * a.x + a.y * a.y + a.z * a.z + a.w * a.w
             + b.x * b.x + b.y * b.y + b.z * b.z + b.w * b.w;
    #pragma unroll
    for (int off = 16; off > 0; off >>= 1) {
        s1 += __shfl_xor_sync(0xffffffffu, s1, off);
        s2 += __shfl_xor_sync(0xffffffffu, s2, off);
    }
    const float mu  = s1 * (1.0f / D_MODEL);
    const float var = s2 * (1.0f / D_MODEL) - mu * mu;
    const float inv = rsqrtf(var + 1e-5f);

    const float4 sa = *reinterpret_cast<const float4*>(&S[c0]);
    const float4 sb = *reinterpret_cast<const float4*>(&S[c0 + 4]);
    const float4 ba = *reinterpret_cast<const float4*>(&Bb[c0]);
    const float4 bb = *reinterpret_cast<const float4*>(&Bb[c0 + 4]);

    __half2 h[4];
    h[0] = __floats2half2_rn((a.x - mu) * inv * sa.x + ba.x, (a.y - mu) * inv * sa.y + ba.y);
    h[1] = __floats2half2_rn((a.z - mu) * inv * sa.z + ba.z, (a.w - mu) * inv * sa.w + ba.w);
    h[2] = __floats2half2_rn((b.x - mu) * inv * sb.x + bb.x, (b.y - mu) * inv * sb.y + bb.y);
    h[3] = __floats2half2_rn((b.z - mu) * inv * sb.z + bb.z, (b.w - mu) * inv * sb.w + bb.w);
    *reinterpret_cast<uint4*>(&Y[row * D_MODEL + c0]) = *reinterpret_cast<uint4*>(h);
}

// ---------------------------------------------------------------------------
// fp16 GEMM: block 64x64, BK=32, 128 threads (2m x 2n warps, 32x32/warp).
// A via ldmatrix.x4, W via ldmatrix.x4.trans.
// 4-stage cp.async pipeline, ONE barrier per K-iteration.
// ---------------------------------------------------------------------------
#define GEMM_SMEM_BYTES (4 * (64 * 40 + 32 * 72) * 2)

template <int MODE>
__device__ __forceinline__ void gemm16_body(
    const __half* __restrict__ A, const __half* __restrict__ W,
    const float* __restrict__ bias, void* Cv, int K, int M, float oscale)
{
    extern __shared__ __align__(16) __half smexh[];
    __half* As = smexh;                  // [4][64*40]
    __half* Ws = smexh + 4 * 64 * 40;    // [4][32*72]

    const int tid  = threadIdx.x;
    const int lane = tid & 31;
    const int wid  = tid >> 5;
    const int warp_m = wid >> 1;
    const int warp_n = wid & 1;
    const int r0   = lane >> 2;
    const int quad = lane & 3;
    const int row0 = blockIdx.y * 64;
    const int col0 = blockIdx.x * 64;

    const int lm_row  = lane & 15;
    const int lm_col8 = (lane >> 4) << 3;

    float acc[2][4][4] = {};

    auto load_stage = [&](int k0, int s) {
        __half* Asb = As + s * (64 * 40);
        #pragma unroll
        for (int i = 0; i < 2; i++) {
            int e = tid + i * 128;
            int r = e >> 2, c8 = e & 3;
            CPA16(smem_u32(&Asb[r * 40 + c8 * 8]),
                  A + (size_t)(row0 + r) * K + k0 + c8 * 8);
        }
        __half* Wsb = Ws + s * (32 * 72);
        #pragma unroll
        for (int i = 0; i < 2; i++) {
            int e = tid + i * 128;
            int r = e >> 3, c8 = e & 7;
            CPA16(smem_u32(&Wsb[r * 72 + c8 * 8]),
                  W + (size_t)(k0 + r) * M + col0 + c8 * 8);
        }
        CPA_COMMIT();
    };

    const int nk = K >> 5;
    load_stage(0, 0);
    load_stage(32, 1);
    load_stage(64, 2);

    for (int it = 0; it < nk; ++it) {
        const int s = it & 3;
        if (it + 2 < nk)      { CPA_WAIT2(); }
        else if (it + 1 < nk) { CPA_WAIT1(); }
        else                  { CPA_WAIT0(); }
        __syncthreads();   // stage it visible; all warps done with slot (it+3)&3
        if (it + 3 < nk) load_stage((it + 3) * 32, (it + 3) & 3);

        const __half* Asb = As + s * (64 * 40);
        const __half* Wsb = Ws + s * (32 * 72);

        #pragma unroll
        for (int ks = 0; ks < 2; ks++) {
            uint32_t a[2][4], b[2][4];
            #pragma unroll
            for (int mi = 0; mi < 2; mi++) {
                const int rb = warp_m * 32 + mi * 16;
                ldsm4(a[mi], smem_u32(&Asb[(rb + lm_row) * 40 + ks * 16 + lm_col8]));
            }
            #pragma unroll
            for (int ni2 = 0; ni2 < 2; ni2++) {
                ldsm4t(b[ni2], smem_u32(&Wsb[(ks * 16 + lm_row) * 72 +
                                             warp_n * 32 + ni2 * 16 + lm_col8]));
            }
            #pragma unroll
            for (int mi = 0; mi < 2; mi++)
                #pragma unroll
                for (int ni2 = 0; ni2 < 2; ni2++) {
                    mma_f16(acc[mi][2 * ni2],     a[mi], &b[ni2][0]);
                    mma_f16(acc[mi][2 * ni2 + 1], a[mi], &b[ni2][2]);
                }
        }
    }

    #pragma unroll
    for (int mi = 0; mi < 2; mi++) {
        #pragma unroll
        for (int ni = 0; ni < 4; ni++) {
            const int r = row0 + warp_m * 32 + mi * 16 + r0;
            const int c = col0 + warp_n * 32 + ni * 8 + 2 * quad;
            const float bx = bias[c], by = bias[c + 1];
            float v0 = acc[mi][ni][0] + bx;
            float v1 = acc[mi][ni][1] + by;
            float v2 = acc[mi][ni][2] + bx;
            float v3 = acc[mi][ni][3] + by;
            if (MODE == 1) {
                v0 = 0.5f * v0 * (1.0f + erff(v0 * 0.70710678118654752f));
                v1 = 0.5f * v1 * (1.0f + erff(v1 * 0.70710678118654752f));
                v2 = 0.5f * v2 * (1.0f + erff(v2 * 0.70710678118654752f));
                v3 = 0.5f * v3 * (1.0f + erff(v3 * 0.70710678118654752f));
            }
            if (MODE == 2) {
                float* Cf = (float*)Cv;
                float2 e0 = *reinterpret_cast<const float2*>(&Cf[(size_t)r * M + c]);
                float2 e1 = *reinterpret_cast<const float2*>(&Cf[(size_t)(r + 8) * M + c]);
                *reinterpret_cast<float2*>(&Cf[(size_t)r * M + c]) =
                    make_float2(v0 + e0.x, v1 + e0.y);
                *reinterpret_cast<float2*>(&Cf[(size_t)(r + 8) * M + c]) =
                    make_float2(v2 + e1.x, v3 + e1.y);
            } else {
                __half* Ch = (__half*)Cv;
                *reinterpret_cast<__half2*>(&Ch[(size_t)r * M + c]) =
                    __floats2half2_rn(v0 * oscale, v1 * oscale);
                *reinterpret_cast<__half2*>(&Ch[(size_t)(r + 8) * M + c]) =
                    __floats2half2_rn(v2 * oscale, v3 * oscale);
            }
        }
    }
}

template <int MODE>
__global__ void __launch_bounds__(128) gemm16_kernel(
    const __half* __restrict__ A, const __half* __restrict__ W,
    const float* __restrict__ bias, void* Cv, int K, int M, float oscale)
{
    gemm16_body<MODE>(A, W, bias, Cv, K, M, oscale);
}

__global__ void __launch_bounds__(128) qkv16_kernel(
    const __half* __restrict__ A,
    const __half* __restrict__ wq, const __half* __restrict__ wk, const __half* __restrict__ wv,
    const float* __restrict__ bq, const float* __restrict__ bk, const float* __restrict__ bv,
    __half* __restrict__ q, __half* __restrict__ k, __half* __restrict__ v, float qscale)
{
    const __half* W; const float* B; __half* C; float os;
    if (blockIdx.z == 0)      { W = wq; B = bq; C = q; os = qscale; }
    else if (blockIdx.z == 1) { W = wk; B = bk; C = k; os = 1.0f; }
    else                      { W = wv; B = bv; C = v; os = 1.0f; }
    gemm16_body<0>(A, W, B, (void*)C, D_MODEL, D_MODEL, os);
}

// ---------------------------------------------------------------------------
// Flash attention fp16: register-resident P, packed-half2 softmax.
// 4-stage KV pipeline, one barrier per iteration.
// ---------------------------------------------------------------------------
#define ATTN_SMEM_BYTES ((128 * 40 + 4 * 2 * (64 * 40)) * 2)

__global__ void __launch_bounds__(128, 4) attn_kernel(
    const __half* __restrict__ Q, const __half* __restrict__ K,
    const __half* __restrict__ V, __half* __restrict__ O)
{
    extern __shared__ __align__(16) __half smexh[];
    __half* Qs = smexh;                    // 128*40
    __half* Ks = Qs + 128 * 40;            // [4][64*40]
    __half* Vs = Ks + 4 * 64 * 40;         // [4][64*40]

    const int tid  = threadIdx.x;
    const int lane = tid & 31;
    const int w    = tid >> 5;
    const int r0   = lane >> 2;
    const int quad = lane & 3;
    const int q0   = blockIdx.x * 128;
    const int h    = blockIdx.y;
    const int b    = blockIdx.z;
    const int base = (b * SEQ) * D_MODEL + h * HEAD_DIM;

    const int lm_row  = lane & 15;
    const int lm_col8 = (lane >> 4) << 3;
    const int lmb_row  = (lane & 7) + ((lane >> 4) << 3);
    const int lmb_col8 = (((lane >> 3) & 1) << 3);

    // Q load (own commit group)
    {
        #pragma unroll
        for (int i = 0; i < 4; i++) {
            int e = tid + i * 128;
            int r = e >> 2, c8 = e & 3;
            CPA16(smem_u32(&Qs[r * 40 + c8 * 8]),
                  &Q[base + (q0 + r) * D_MODEL + c8 * 8]);
        }
        CPA_COMMIT();
    }

    auto load_kv = [&](int kt, int s) {
        __half* Ksb = Ks + s * (64 * 40);
        __half* Vsb = Vs + s * (64 * 40);
        #pragma unroll
        for (int i = 0; i < 2; i++) {
            const int e = tid + i * 128;
            const int r = e >> 2, c8 = e & 3;
            CPA16(smem_u32(&Ksb[r * 40 + c8 * 8]), &K[base + (kt + r) * D_MODEL + c8 * 8]);
            CPA16(smem_u32(&Vsb[r * 40 + c8 * 8]), &V[base + (kt + r) * D_MODEL + c8 * 8]);
        }
        CPA_COMMIT();
    };

    load_kv(0, 0);
    load_kv(64, 1);
    load_kv(128, 2);

    CPA_WAIT3();
    __syncthreads();
    uint32_t qf[2][2][4];
    #pragma unroll
    for (int mi = 0; mi < 2; mi++) {
        const int rb = w * 32 + mi * 16;
        #pragma unroll
        for (int ks = 0; ks < 2; ks++)
            ldsm4(qf[mi][ks], smem_u32(&Qs[(rb + lm_row) * 40 + ks * 16 + lm_col8]));
    }

    float m[2][2], o[2][4][4] = {}, oE[2][4] = {};
    #pragma unroll
    for (int mi = 0; mi < 2; mi++) { m[mi][0] = m[mi][1] = -1e30f; }

    const uint32_t onesfrag[2] = {0x3C003C00u, 0x3C003C00u};

    const int NIT = SEQ / 64;
    for (int it = 0; it < NIT; ++it) {
        const int s = it & 3;
        if (it + 2 < NIT)      { CPA_WAIT2(); }
        else if (it + 1 < NIT) { CPA_WAIT1(); }
        else                   { CPA_WAIT0(); }
        __syncthreads();
        if (it + 3 < NIT) load_kv((it + 3) * 64, (it + 3) & 3);

        const __half* Ksb = Ks + s * (64 * 40);
        const __half* Vsb = Vs + s * (64 * 40);

        // S = Q K^T (log2-domain scores via pre-scaled Q)
        float sc[2][8][4] = {};
        #pragma unroll
        for (int ks = 0; ks < 2; ks++) {
            uint32_t bfr[4][4];
            #pragma unroll
            for (int nq = 0; nq < 4; nq++)
                ldsm4(bfr[nq], smem_u32(&Ksb[(nq * 16 + lmb_row) * 40 +
                                             ks * 16 + lmb_col8]));
            #pragma unroll
            for (int mi = 0; mi < 2; mi++)
                #pragma unroll
                for (int nq = 0; nq < 4; nq++) {
                    mma_f16(sc[mi][2 * nq],     qf[mi][ks], &bfr[nq][0]);
                    mma_f16(sc[mi][2 * nq + 1], qf[mi][ks], &bfr[nq][2]);
                }
        }

        // Softmax in packed half2: pack -> hmax2 tree -> quad shfl -> hsub2+ex2.f16x2
        uint32_t pa[2][4][4];
        #pragma unroll
        for (int mi = 0; mi < 2; mi++) {
            // pack: hA[ni] = (rowA c, rowA c+1), hB[ni] = (rowB c, rowB c+1)
            uint32_t hA[8], hB[8];
            #pragma unroll
            for (int ni = 0; ni < 8; ni++) {
                hA[ni] = f22h2(sc[mi][ni][0], sc[mi][ni][1]);
                hB[ni] = f22h2(sc[mi][ni][2], sc[mi][ni][3]);
            }
            // max trees
            uint32_t mA = hA[0], mB = hB[0];
            #pragma unroll
            for (int ni = 1; ni < 8; ni++) { mA = hmax2u(mA, hA[ni]); mB = hmax2u(mB, hB[ni]); }
            mA = hmax2u(mA, __byte_perm(mA, mA, 0x1032));   // horizontal max rowA
            mB = hmax2u(mB, __byte_perm(mB, mB, 0x1032));   // horizontal max rowB
            uint32_t mAB = __byte_perm(mA, mB, 0x5410);     // (rowA max, rowB max)
            #pragma unroll
            for (int off = 1; off < 4; off <<= 1)
                mAB = hmax2u(mAB, __shfl_xor_sync(0xffffffffu, mAB, off));
            __half2 mh = *reinterpret_cast<__half2*>(&mAB);
            const float mt0 = __low2float(mh);
            const float mt1 = __high2float(mh);

            const float mn0 = fmaxf(m[mi][0], mt0);
            const float mn1 = fmaxf(m[mi][1], mt1);
            const float alpha0 = ex2(m[mi][0] - mn0);
            const float alpha1 = ex2(m[mi][1] - mn1);
            m[mi][0] = mn0; m[mi][1] = mn1;

            const uint32_t mn0h2 = f22h2(mn0, mn0);
            const uint32_t mn1h2 = f22h2(mn1, mn1);
            #pragma unroll
            for (int ks = 0; ks < 4; ks++) {
                pa[mi][ks][0] = hex2u(hsub2u(hA[2 * ks],     mn0h2));
                pa[mi][ks][1] = hex2u(hsub2u(hB[2 * ks],     mn1h2));
                pa[mi][ks][2] = hex2u(hsub2u(hA[2 * ks + 1], mn0h2));
                pa[mi][ks][3] = hex2u(hsub2u(hB[2 * ks + 1], mn1h2));
            }
            #pragma unroll
            for (int ni = 0; ni < 4; ni++) {
                o[mi][ni][0] *= alpha0; o[mi][ni][1] *= alpha0;
                o[mi][ni][2] *= alpha1; o[mi][ni][3] *= alpha1;
            }
            oE[mi][0] *= alpha0; oE[mi][1] *= alpha0;
            oE[mi][2] *= alpha1; oE[mi][3] *= alpha1;
        }

        // O += P @ V ; l += P @ ones
        #pragma unroll
        for (int ks = 0; ks < 4; ks++) {
            uint32_t b[2][4];
            #pragma unroll
            for (int ni2 = 0; ni2 < 2; ni2++)
                ldsm4t(b[ni2], smem_u32(&Vsb[(ks * 16 + lm_row) * 40 +
                                             ni2 * 16 + lm_col8]));
            #pragma unroll
            for (int mi = 0; mi < 2; mi++) {
                #pragma unroll
                for (int ni2 = 0; ni2 < 2; ni2++) {
                    mma_f16(o[mi][2 * ni2],     pa[mi][ks], &b[ni2][0]);
                    mma_f16(o[mi][2 * ni2 + 1], pa[mi][ks], &b[ni2][2]);
                }
                mma_f16(oE[mi], pa[mi][ks], onesfrag);
            }
        }
    }

    #pragma unroll
    for (int mi = 0; mi < 2; mi++) {
        const float inv0 = 1.0f / oE[mi][0];
        const float inv1 = 1.0f / oE[mi][2];
        const int q = q0 + w * 32 + mi * 16 + r0;
        #pragma unroll
        for (int ni = 0; ni < 4; ni++) {
            const int d = ni * 8 + 2 * quad;
            *reinterpret_cast<__half2*>(&O[base + q * D_MODEL + d]) =
                __floats2half2_rn(o[mi][ni][0] * inv0, o[mi][ni][1] * inv0);
            *reinterpret_cast<__half2*>(&O[base + (q + 8) * D_MODEL + d]) =
                __floats2half2_rn(o[mi][ni][2] * inv1, o[mi][ni][3] * inv1);
        }
    }
}

// ---------------------------------------------------------------------------
// Launch
// ---------------------------------------------------------------------------
extern "C" void kernel_launch(void* const* d_in, const int* in_sizes, int n_in,
                              void* d_out, int out_size)
{
    const float* x    = (const float*)d_in[0];
    const float* ln1s = (const float*)d_in[1];
    const float* ln1b = (const float*)d_in[2];
    const float* wq   = (const float*)d_in[3];
    const float* bq   = (const float*)d_in[4];
    const float* wk   = (const float*)d_in[5];
    const float* bk   = (const float*)d_in[6];
    const float* wv   = (const float*)d_in[7];
    const float* bv   = (const float*)d_in[8];
    const float* wo   = (const float*)d_in[9];
    const float* bo   = (const float*)d_in[10];
    const float* ln2s = (const float*)d_in[11];
    const float* ln2b = (const float*)d_in[12];
    const float* w1   = (const float*)d_in[13];
    const float* b1   = (const float*)d_in[14];
    const float* w2   = (const float*)d_in[15];
    const float* b2   = (const float*)d_in[16];

    float* X = (float*)d_out;

    __half *normed, *q, *k, *v, *attn, *ffh;
    __half *wq16, *wk16, *wv16, *wo16, *w116, *w216;
    cudaGetSymbolAddress((void**)&normed, g_normed);
    cudaGetSymbolAddress((void**)&q,      g_q);
    cudaGetSymbolAddress((void**)&k,      g_k);
    cudaGetSymbolAddress((void**)&v,      g_v);
    cudaGetSymbolAddress((void**)&attn,   g_attn);
    cudaGetSymbolAddress((void**)&ffh,    g_ffh);
    cudaGetSymbolAddress((void**)&wq16,   g_wq16);
    cudaGetSymbolAddress((void**)&wk16,   g_wk16);
    cudaGetSymbolAddress((void**)&wv16,   g_wv16);
    cudaGetSymbolAddress((void**)&wo16,   g_wo16);
    cudaGetSymbolAddress((void**)&w116,   g_w116);
    cudaGetSymbolAddress((void**)&w216,   g_w216);

    cudaFuncSetAttribute(attn_kernel,
                         cudaFuncAttributeMaxDynamicSharedMemorySize, ATTN_SMEM_BYTES);

    cudaMemcpyAsync(X, x, (size_t)NTOK * D_MODEL * sizeof(float),
                    cudaMemcpyDeviceToDevice);

    cvt_all_kernel<<<(TOT4 + 255) / 256, 256>>>(wq, wk, wv, wo, w1, w2,
                                                wq16, wk16, wv16, wo16, w116, w216);

    const float qscale = 0.17677669529663687f * 1.4426950408889634f;

    const dim3 gemm_dd(D_MODEL / 64, NTOK / 64);
    const dim3 gemm_df(D_FF / 64,    NTOK / 64);
    const dim3 qkv_grid(D_MODEL / 64, NTOK / 64, 3);
    const dim3 attn_grid(SEQ / 128, N_HEADS, BATCH);

    for (int ly = 0; ly < N_LAYERS; ly++) {
        const int wdd = ly * D_MODEL * D_MODEL;
        const int wdf = ly * D_MODEL * D_FF;

        ln_kernel<<<NTOK / 8, 256>>>(X, ln1s + ly * D_MODEL, ln1b + ly * D_MODEL, normed);

        qkv16_kernel<<<qkv_grid, 128, GEMM_SMEM_BYTES>>>(
            normed, wq16 + wdd, wk16 + wdd, wv16 + wdd,
            bq + ly * D_MODEL, bk + ly * D_MODEL, bv + ly * D_MODEL,
            q, k, v, qscale);

        attn_kernel<<<attn_grid, 128, ATTN_SMEM_BYTES>>>(q, k, v, attn);

        gemm16_kernel<2><<<gemm_dd, 128, GEMM_SMEM_BYTES>>>(
            attn, wo16 + wdd, bo + ly * D_MODEL, (void*)X, D_MODEL, D_MODEL, 1.0f);

        ln_kernel<<<NTOK / 8, 256>>>(X, ln2s + ly * D_MODEL, ln2b + ly * D_MODEL, normed);

        gemm16_kernel<1><<<gemm_df, 128, GEMM_SMEM_BYTES>>>(
            normed, w116 + wdf, b1 + ly * D_FF, (void*)ffh, D_MODEL, D_FF, 1.0f);

        gemm16_kernel<2><<<gemm_dd, 128, GEMM_SMEM_BYTES>>>(
            ffh, w216 + wdf, b2 + ly * D_MODEL, (void*)X, D_FF, D_MODEL, 1.0f);
    }
}

// round 11
// speedup vs baseline: 2.0304x; 1.0577x over previous
#include <cuda_runtime.h>
#include <cuda_fp16.h>
#include <math.h>
#include <stdint.h>

#define D_MODEL   256
#define N_LAYERS  6
#define N_HEADS   8
#define D_FF      1024
#define HEAD_DIM  32
#define BATCH     4
#define SEQ       2048
#define NTOK      (BATCH * SEQ)   // 8192

// ---------------------------------------------------------------------------
// Scratch (fp16 activations + fp16 weight shadows)
// ---------------------------------------------------------------------------
__device__ __align__(16) __half g_normed[NTOK * D_MODEL];
__device__ __align__(16) __half g_q[NTOK * D_MODEL];
__device__ __align__(16) __half g_k[NTOK * D_MODEL];
__device__ __align__(16) __half g_v[NTOK * D_MODEL];
__device__ __align__(16) __half g_attn[NTOK * D_MODEL];
__device__ __align__(16) __half g_ffh[NTOK * D_FF];

__device__ __align__(16) __half g_wq16[N_LAYERS * D_MODEL * D_MODEL];
__device__ __align__(16) __half g_wk16[N_LAYERS * D_MODEL * D_MODEL];
__device__ __align__(16) __half g_wv16[N_LAYERS * D_MODEL * D_MODEL];
__device__ __align__(16) __half g_wo16[N_LAYERS * D_MODEL * D_MODEL];
__device__ __align__(16) __half g_w116[N_LAYERS * D_MODEL * D_FF];
__device__ __align__(16) __half g_w216[N_LAYERS * D_FF * D_MODEL];

// ---------------------------------------------------------------------------
// Helpers
// ---------------------------------------------------------------------------
__device__ __forceinline__ uint32_t smem_u32(const void* p) {
    return (uint32_t)__cvta_generic_to_shared(p);
}
#define CPA16(dst_u32, src_ptr) \
    asm volatile("cp.async.cg.shared.global [%0], [%1], 16;\n" :: "r"(dst_u32), "l"(src_ptr))
#define CPA_COMMIT() asm volatile("cp.async.commit_group;\n" ::)
#define CPA_WAIT3()  asm volatile("cp.async.wait_group 3;\n" ::)
#define CPA_WAIT2()  asm volatile("cp.async.wait_group 2;\n" ::)
#define CPA_WAIT1()  asm volatile("cp.async.wait_group 1;\n" ::)
#define CPA_WAIT0()  asm volatile("cp.async.wait_group 0;\n" ::)

// HMMA m16n8k16 fp16 -> fp32 accum
__device__ __forceinline__ void mma_f16(float* c, const uint32_t* a, const uint32_t* b) {
    asm volatile(
        "mma.sync.aligned.m16n8k16.row.col.f32.f16.f16.f32 "
        "{%0,%1,%2,%3},{%4,%5,%6,%7},{%8,%9},{%0,%1,%2,%3};\n"
        : "+f"(c[0]), "+f"(c[1]), "+f"(c[2]), "+f"(c[3])
        : "r"(a[0]), "r"(a[1]), "r"(a[2]), "r"(a[3]),
          "r"(b[0]), "r"(b[1]));
}

__device__ __forceinline__ void ldsm4(uint32_t* r, uint32_t byte_addr) {
    asm volatile("ldmatrix.sync.aligned.m8n8.x4.shared.b16 {%0,%1,%2,%3}, [%4];\n"
        : "=r"(r[0]), "=r"(r[1]), "=r"(r[2]), "=r"(r[3]) : "r"(byte_addr));
}
__device__ __forceinline__ void ldsm4t(uint32_t* r, uint32_t byte_addr) {
    asm volatile("ldmatrix.sync.aligned.m8n8.x4.trans.shared.b16 {%0,%1,%2,%3}, [%4];\n"
        : "=r"(r[0]), "=r"(r[1]), "=r"(r[2]), "=r"(r[3]) : "r"(byte_addr));
}

__device__ __forceinline__ float ex2(float x) {
    float y;
    asm("ex2.approx.f32 %0, %1;" : "=f"(y) : "f"(x));
    return y;
}
// packed-half2 primitives for softmax
__device__ __forceinline__ uint32_t f22h2(float lo, float hi) {
    __half2 h = __floats2half2_rn(lo, hi);
    return *reinterpret_cast<uint32_t*>(&h);
}
__device__ __forceinline__ uint32_t hmax2u(uint32_t a, uint32_t b) {
    uint32_t d;
    asm("max.f16x2 %0, %1, %2;" : "=r"(d) : "r"(a), "r"(b));
    return d;
}
__device__ __forceinline__ uint32_t hsub2u(uint32_t a, uint32_t b) {
    uint32_t d;
    asm("sub.f16x2 %0, %1, %2;" : "=r"(d) : "r"(a), "r"(b));
    return d;
}
__device__ __forceinline__ uint32_t hex2u(uint32_t a) {
    uint32_t d;
    asm("ex2.approx.f16x2 %0, %1;" : "=r"(d) : "r"(a));
    return d;
}

// ---------------------------------------------------------------------------
// Merged fp32 -> fp16 weight conversion
// ---------------------------------------------------------------------------
#define DD4 (N_LAYERS * D_MODEL * D_MODEL / 4)
#define DF4 (N_LAYERS * D_MODEL * D_FF / 4)
#define TOT4 (4 * DD4 + 2 * DF4)

__global__ void __launch_bounds__(256) cvt_all_kernel(
    const float* __restrict__ wq, const float* __restrict__ wk,
    const float* __restrict__ wv, const float* __restrict__ wo,
    const float* __restrict__ w1, const float* __restrict__ w2,
    __half* __restrict__ wq16, __half* __restrict__ wk16,
    __half* __restrict__ wv16, __half* __restrict__ wo16,
    __half* __restrict__ w116, __half* __restrict__ w216)
{
    const int i = blockIdx.x * blockDim.x + threadIdx.x;
    if (i >= TOT4) return;
    const float* src; __half* dst; int off;
    if (i < DD4)          { src = wq; dst = wq16; off = i; }
    else if (i < 2 * DD4) { src = wk; dst = wk16; off = i - DD4; }
    else if (i < 3 * DD4) { src = wv; dst = wv16; off = i - 2 * DD4; }
    else if (i < 4 * DD4) { src = wo; dst = wo16; off = i - 3 * DD4; }
    else if (i < 4 * DD4 + DF4) { src = w1; dst = w116; off = i - 4 * DD4; }
    else                  { src = w2; dst = w216; off = i - 4 * DD4 - DF4; }
    float4 v = reinterpret_cast<const float4*>(src)[off];
    __half2 h0 = __floats2half2_rn(v.x, v.y);
    __half2 h1 = __floats2half2_rn(v.z, v.w);
    reinterpret_cast<__half2*>(dst)[2 * off]     = h0;
    reinterpret_cast<__half2*>(dst)[2 * off + 1] = h1;
}

// ---------------------------------------------------------------------------
// LayerNorm: warp per row, float4 loads, fp16 out.
// ---------------------------------------------------------------------------
__global__ void __launch_bounds__(256) ln_kernel(
    const float* __restrict__ X, const float* __restrict__ S,
    const float* __restrict__ Bb, __half* __restrict__ Y)
{
    const int row  = blockIdx.x * 8 + (threadIdx.x >> 5);
    const int lane = threadIdx.x & 31;
    const int c0   = lane * 8;

    const float4 a = *reinterpret_cast<const float4*>(&X[row * D_MODEL + c0]);
    const float4 b = *reinterpret_cast<const float4*>(&X[row * D_MODEL + c0 + 4]);

    float s1 = a.x + a.y + a.z + a.w + b.x + b.y + b.z + b.w;
    float s2 = a.x * a.x + a.y * a.y + a.z * a.z + a.w * a.w
             + b.x * b.x + b.y * b.y + b.z * b.z + b.w * b.w;
    #pragma unroll
    for (int off = 16; off > 0; off >>= 1) {
        s1 += __shfl_xor_sync(0xffffffffu, s1, off);
        s2 += __shfl_xor_sync(0xffffffffu, s2, off);
    }
    const float mu  = s1 * (1.0f / D_MODEL);
    const float var = s2 * (1.0f / D_MODEL) - mu * mu;
    const float inv = rsqrtf(var + 1e-5f);

    const float4 sa = *reinterpret_cast<const float4*>(&S[c0]);
    const float4 sb = *reinterpret_cast<const float4*>(&S[c0 + 4]);
    const float4 ba = *reinterpret_cast<const float4*>(&Bb[c0]);
    const float4 bb = *reinterpret_cast<const float4*>(&Bb[c0 + 4]);

    __half2 h[4];
    h[0] = __floats2half2_rn((a.x - mu) * inv * sa.x + ba.x, (a.y - mu) * inv * sa.y + ba.y);
    h[1] = __floats2half2_rn((a.z - mu) * inv * sa.z + ba.z, (a.w - mu) * inv * sa.w + ba.w);
    h[2] = __floats2half2_rn((b.x - mu) * inv * sb.x + bb.x, (b.y - mu) * inv * sb.y + bb.y);
    h[3] = __floats2half2_rn((b.z - mu) * inv * sb.z + bb.z, (b.w - mu) * inv * sb.w + bb.w);
    *reinterpret_cast<uint4*>(&Y[row * D_MODEL + c0]) = *reinterpret_cast<uint4*>(h);
}

// ---------------------------------------------------------------------------
// fp16 GEMM: block 64x64, BK=64, 128 threads (2m x 2n warps, 32x32/warp).
// A via ldmatrix.x4, W via ldmatrix.x4.trans.
// 3-stage cp.async pipeline, ONE barrier per K-iteration (4 ks-steps each).
// smem: 3 * 2 * (64*72) halves = 55296 B
// ---------------------------------------------------------------------------
#define GEMM_SMEM_BYTES (3 * 2 * (64 * 72) * 2)

template <int MODE>
__device__ __forceinline__ void gemm16_body(
    const __half* __restrict__ A, const __half* __restrict__ W,
    const float* __restrict__ bias, void* Cv, int K, int M, float oscale)
{
    extern __shared__ __align__(16) __half smexh[];
    __half* As = smexh;                  // [3][64*72]
    __half* Ws = smexh + 3 * 64 * 72;    // [3][64*72]

    const int tid  = threadIdx.x;
    const int lane = tid & 31;
    const int wid  = tid >> 5;
    const int warp_m = wid >> 1;
    const int warp_n = wid & 1;
    const int r0   = lane >> 2;
    const int quad = lane & 3;
    const int row0 = blockIdx.y * 64;
    const int col0 = blockIdx.x * 64;

    const int lm_row  = lane & 15;
    const int lm_col8 = (lane >> 4) << 3;

    float acc[2][4][4] = {};

    auto load_stage = [&](int k0, int s) {
        __half* Asb = As + s * (64 * 72);
        __half* Wsb = Ws + s * (64 * 72);
        #pragma unroll
        for (int i = 0; i < 4; i++) {
            int e = tid + i * 128;          // 0..511
            int r = e >> 3, c8 = e & 7;     // 64 rows x 8 chunks
            CPA16(smem_u32(&Asb[r * 72 + c8 * 8]),
                  A + (size_t)(row0 + r) * K + k0 + c8 * 8);
            CPA16(smem_u32(&Wsb[r * 72 + c8 * 8]),
                  W + (size_t)(k0 + r) * M + col0 + c8 * 8);
        }
        CPA_COMMIT();
    };

    const int nk = K >> 6;                  // BK = 64
    load_stage(0, 0);
    if (nk > 1) load_stage(64, 1);

    for (int it = 0; it < nk; ++it) {
        const int s = it % 3;
        if (it + 1 < nk) { CPA_WAIT1(); }
        else             { CPA_WAIT0(); }
        __syncthreads();   // stage it visible; all warps done with slot (it+2)%3
        if (it + 2 < nk) load_stage((it + 2) * 64, (it + 2) % 3);

        const __half* Asb = As + s * (64 * 72);
        const __half* Wsb = Ws + s * (64 * 72);

        #pragma unroll
        for (int ks = 0; ks < 4; ks++) {    // four k=16 steps
            uint32_t a[2][4], b[2][4];
            #pragma unroll
            for (int mi = 0; mi < 2; mi++) {
                const int rb = warp_m * 32 + mi * 16;
                ldsm4(a[mi], smem_u32(&Asb[(rb + lm_row) * 72 + ks * 16 + lm_col8]));
            }
            #pragma unroll
            for (int ni2 = 0; ni2 < 2; ni2++) {
                ldsm4t(b[ni2], smem_u32(&Wsb[(ks * 16 + lm_row) * 72 +
                                             warp_n * 32 + ni2 * 16 + lm_col8]));
            }
            #pragma unroll
            for (int mi = 0; mi < 2; mi++)
                #pragma unroll
                for (int ni2 = 0; ni2 < 2; ni2++) {
                    mma_f16(acc[mi][2 * ni2],     a[mi], &b[ni2][0]);
                    mma_f16(acc[mi][2 * ni2 + 1], a[mi], &b[ni2][2]);
                }
        }
    }

    #pragma unroll
    for (int mi = 0; mi < 2; mi++) {
        #pragma unroll
        for (int ni = 0; ni < 4; ni++) {
            const int r = row0 + warp_m * 32 + mi * 16 + r0;
            const int c = col0 + warp_n * 32 + ni * 8 + 2 * quad;
            const float bx = bias[c], by = bias[c + 1];
            float v0 = acc[mi][ni][0] + bx;
            float v1 = acc[mi][ni][1] + by;
            float v2 = acc[mi][ni][2] + bx;
            float v3 = acc[mi][ni][3] + by;
            if (MODE == 1) {
                v0 = 0.5f * v0 * (1.0f + erff(v0 * 0.70710678118654752f));
                v1 = 0.5f * v1 * (1.0f + erff(v1 * 0.70710678118654752f));
                v2 = 0.5f * v2 * (1.0f + erff(v2 * 0.70710678118654752f));
                v3 = 0.5f * v3 * (1.0f + erff(v3 * 0.70710678118654752f));
            }
            if (MODE == 2) {
                float* Cf = (float*)Cv;
                float2 e0 = *reinterpret_cast<const float2*>(&Cf[(size_t)r * M + c]);
                float2 e1 = *reinterpret_cast<const float2*>(&Cf[(size_t)(r + 8) * M + c]);
                *reinterpret_cast<float2*>(&Cf[(size_t)r * M + c]) =
                    make_float2(v0 + e0.x, v1 + e0.y);
                *reinterpret_cast<float2*>(&Cf[(size_t)(r + 8) * M + c]) =
                    make_float2(v2 + e1.x, v3 + e1.y);
            } else {
                __half* Ch = (__half*)Cv;
                *reinterpret_cast<__half2*>(&Ch[(size_t)r * M + c]) =
                    __floats2half2_rn(v0 * oscale, v1 * oscale);
                *reinterpret_cast<__half2*>(&Ch[(size_t)(r + 8) * M + c]) =
                    __floats2half2_rn(v2 * oscale, v3 * oscale);
            }
        }
    }
}

template <int MODE>
__global__ void __launch_bounds__(128) gemm16_kernel(
    const __half* __restrict__ A, const __half* __restrict__ W,
    const float* __restrict__ bias, void* Cv, int K, int M, float oscale)
{
    gemm16_body<MODE>(A, W, bias, Cv, K, M, oscale);
}

__global__ void __launch_bounds__(128) qkv16_kernel(
    const __half* __restrict__ A,
    const __half* __restrict__ wq, const __half* __restrict__ wk, const __half* __restrict__ wv,
    const float* __restrict__ bq, const float* __restrict__ bk, const float* __restrict__ bv,
    __half* __restrict__ q, __half* __restrict__ k, __half* __restrict__ v, float qscale)
{
    const __half* W; const float* B; __half* C; float os;
    if (blockIdx.z == 0)      { W = wq; B = bq; C = q; os = qscale; }
    else if (blockIdx.z == 1) { W = wk; B = bk; C = k; os = 1.0f; }
    else                      { W = wv; B = bv; C = v; os = 1.0f; }
    gemm16_body<0>(A, W, B, (void*)C, D_MODEL, D_MODEL, os);
}

// ---------------------------------------------------------------------------
// Flash attention fp16: register-resident P, packed-half2 softmax,
// warp-uniform alpha-skip (exact), 4-stage KV pipeline, 1 barrier/iter.
// ---------------------------------------------------------------------------
#define ATTN_SMEM_BYTES ((128 * 40 + 4 * 2 * (64 * 40)) * 2)

__global__ void __launch_bounds__(128, 4) attn_kernel(
    const __half* __restrict__ Q, const __half* __restrict__ K,
    const __half* __restrict__ V, __half* __restrict__ O)
{
    extern __shared__ __align__(16) __half smexh[];
    __half* Qs = smexh;                    // 128*40
    __half* Ks = Qs + 128 * 40;            // [4][64*40]
    __half* Vs = Ks + 4 * 64 * 40;         // [4][64*40]

    const int tid  = threadIdx.x;
    const int lane = tid & 31;
    const int w    = tid >> 5;
    const int r0   = lane >> 2;
    const int quad = lane & 3;
    const int q0   = blockIdx.x * 128;
    const int h    = blockIdx.y;
    const int b    = blockIdx.z;
    const int base = (b * SEQ) * D_MODEL + h * HEAD_DIM;

    const int lm_row  = lane & 15;
    const int lm_col8 = (lane >> 4) << 3;
    const int lmb_row  = (lane & 7) + ((lane >> 4) << 3);
    const int lmb_col8 = (((lane >> 3) & 1) << 3);

    // Q load (own commit group)
    {
        #pragma unroll
        for (int i = 0; i < 4; i++) {
            int e = tid + i * 128;
            int r = e >> 2, c8 = e & 3;
            CPA16(smem_u32(&Qs[r * 40 + c8 * 8]),
                  &Q[base + (q0 + r) * D_MODEL + c8 * 8]);
        }
        CPA_COMMIT();
    }

    auto load_kv = [&](int kt, int s) {
        __half* Ksb = Ks + s * (64 * 40);
        __half* Vsb = Vs + s * (64 * 40);
        #pragma unroll
        for (int i = 0; i < 2; i++) {
            const int e = tid + i * 128;
            const int r = e >> 2, c8 = e & 3;
            CPA16(smem_u32(&Ksb[r * 40 + c8 * 8]), &K[base + (kt + r) * D_MODEL + c8 * 8]);
            CPA16(smem_u32(&Vsb[r * 40 + c8 * 8]), &V[base + (kt + r) * D_MODEL + c8 * 8]);
        }
        CPA_COMMIT();
    };

    load_kv(0, 0);
    load_kv(64, 1);
    load_kv(128, 2);

    CPA_WAIT3();
    __syncthreads();
    uint32_t qf[2][2][4];
    #pragma unroll
    for (int mi = 0; mi < 2; mi++) {
        const int rb = w * 32 + mi * 16;
        #pragma unroll
        for (int ks = 0; ks < 2; ks++)
            ldsm4(qf[mi][ks], smem_u32(&Qs[(rb + lm_row) * 40 + ks * 16 + lm_col8]));
    }

    float m[2][2], o[2][4][4] = {}, oE[2][4] = {};
    #pragma unroll
    for (int mi = 0; mi < 2; mi++) { m[mi][0] = m[mi][1] = -1e30f; }

    const uint32_t onesfrag[2] = {0x3C003C00u, 0x3C003C00u};

    const int NIT = SEQ / 64;
    for (int it = 0; it < NIT; ++it) {
        const int s = it & 3;
        if (it + 2 < NIT)      { CPA_WAIT2(); }
        else if (it + 1 < NIT) { CPA_WAIT1(); }
        else                   { CPA_WAIT0(); }
        __syncthreads();
        if (it + 3 < NIT) load_kv((it + 3) * 64, (it + 3) & 3);

        const __half* Ksb = Ks + s * (64 * 40);
        const __half* Vsb = Vs + s * (64 * 40);

        // S = Q K^T (log2-domain scores via pre-scaled Q)
        float sc[2][8][4] = {};
        #pragma unroll
        for (int ks = 0; ks < 2; ks++) {
            uint32_t bfr[4][4];
            #pragma unroll
            for (int nq = 0; nq < 4; nq++)
                ldsm4(bfr[nq], smem_u32(&Ksb[(nq * 16 + lmb_row) * 40 +
                                             ks * 16 + lmb_col8]));
            #pragma unroll
            for (int mi = 0; mi < 2; mi++)
                #pragma unroll
                for (int nq = 0; nq < 4; nq++) {
                    mma_f16(sc[mi][2 * nq],     qf[mi][ks], &bfr[nq][0]);
                    mma_f16(sc[mi][2 * nq + 1], qf[mi][ks], &bfr[nq][2]);
                }
        }

        // Softmax in packed half2 with warp-uniform alpha-skip
        uint32_t pa[2][4][4];
        #pragma unroll
        for (int mi = 0; mi < 2; mi++) {
            uint32_t hA[8], hB[8];
            #pragma unroll
            for (int ni = 0; ni < 8; ni++) {
                hA[ni] = f22h2(sc[mi][ni][0], sc[mi][ni][1]);
                hB[ni] = f22h2(sc[mi][ni][2], sc[mi][ni][3]);
            }
            uint32_t mA = hA[0], mB = hB[0];
            #pragma unroll
            for (int ni = 1; ni < 8; ni++) { mA = hmax2u(mA, hA[ni]); mB = hmax2u(mB, hB[ni]); }
            mA = hmax2u(mA, __byte_perm(mA, mA, 0x1032));
            mB = hmax2u(mB, __byte_perm(mB, mB, 0x1032));
            uint32_t mAB = __byte_perm(mA, mB, 0x5410);
            #pragma unroll
            for (int off = 1; off < 4; off <<= 1)
                mAB = hmax2u(mAB, __shfl_xor_sync(0xffffffffu, mAB, off));
            __half2 mh = *reinterpret_cast<__half2*>(&mAB);
            const float mt0 = __low2float(mh);
            const float mt1 = __high2float(mh);

            const float mn0 = fmaxf(m[mi][0], mt0);
            const float mn1 = fmaxf(m[mi][1], mt1);
            // Exact skip: if neither row's max changed, alpha == 1.0 exactly.
            const bool unchanged = (mn0 == m[mi][0]) && (mn1 == m[mi][1]);
            if (!__all_sync(0xffffffffu, unchanged)) {
                const float alpha0 = ex2(m[mi][0] - mn0);
                const float alpha1 = ex2(m[mi][1] - mn1);
                #pragma unroll
                for (int ni = 0; ni < 4; ni++) {
                    o[mi][ni][0] *= alpha0; o[mi][ni][1] *= alpha0;
                    o[mi][ni][2] *= alpha1; o[mi][ni][3] *= alpha1;
                }
                oE[mi][0] *= alpha0; oE[mi][1] *= alpha0;
                oE[mi][2] *= alpha1; oE[mi][3] *= alpha1;
            }
            m[mi][0] = mn0; m[mi][1] = mn1;

            const uint32_t mn0h2 = f22h2(mn0, mn0);
            const uint32_t mn1h2 = f22h2(mn1, mn1);
            #pragma unroll
            for (int ks = 0; ks < 4; ks++) {
                pa[mi][ks][0] = hex2u(hsub2u(hA[2 * ks],     mn0h2));
                pa[mi][ks][1] = hex2u(hsub2u(hB[2 * ks],     mn1h2));
                pa[mi][ks][2] = hex2u(hsub2u(hA[2 * ks + 1], mn0h2));
                pa[mi][ks][3] = hex2u(hsub2u(hB[2 * ks + 1], mn1h2));
            }
        }

        // O += P @ V ; l += P @ ones
        #pragma unroll
        for (int ks = 0; ks < 4; ks++) {
            uint32_t b[2][4];
            #pragma unroll
            for (int ni2 = 0; ni2 < 2; ni2++)
                ldsm4t(b[ni2], smem_u32(&Vsb[(ks * 16 + lm_row) * 40 +
                                             ni2 * 16 + lm_col8]));
            #pragma unroll
            for (int mi = 0; mi < 2; mi++) {
                #pragma unroll
                for (int ni2 = 0; ni2 < 2; ni2++) {
                    mma_f16(o[mi][2 * ni2],     pa[mi][ks], &b[ni2][0]);
                    mma_f16(o[mi][2 * ni2 + 1], pa[mi][ks], &b[ni2][2]);
                }
                mma_f16(oE[mi], pa[mi][ks], onesfrag);
            }
        }
    }

    #pragma unroll
    for (int mi = 0; mi < 2; mi++) {
        const float inv0 = 1.0f / oE[mi][0];
        const float inv1 = 1.0f / oE[mi][2];
        const int q = q0 + w * 32 + mi * 16 + r0;
        #pragma unroll
        for (int ni = 0; ni < 4; ni++) {
            const int d = ni * 8 + 2 * quad;
            *reinterpret_cast<__half2*>(&O[base + q * D_MODEL + d]) =
                __floats2half2_rn(o[mi][ni][0] * inv0, o[mi][ni][1] * inv0);
            *reinterpret_cast<__half2*>(&O[base + (q + 8) * D_MODEL + d]) =
                __floats2half2_rn(o[mi][ni][2] * inv1, o[mi][ni][3] * inv1);
        }
    }
}

// ---------------------------------------------------------------------------
// Launch
// ---------------------------------------------------------------------------
extern "C" void kernel_launch(void* const* d_in, const int* in_sizes, int n_in,
                              void* d_out, int out_size)
{
    const float* x    = (const float*)d_in[0];
    const float* ln1s = (const float*)d_in[1];
    const float* ln1b = (const float*)d_in[2];
    const float* wq   = (const float*)d_in[3];
    const float* bq   = (const float*)d_in[4];
    const float* wk   = (const float*)d_in[5];
    const float* bk   = (const float*)d_in[6];
    const float* wv   = (const float*)d_in[7];
    const float* bv   = (const float*)d_in[8];
    const float* wo   = (const float*)d_in[9];
    const float* bo   = (const float*)d_in[10];
    const float* ln2s = (const float*)d_in[11];
    const float* ln2b = (const float*)d_in[12];
    const float* w1   = (const float*)d_in[13];
    const float* b1   = (const float*)d_in[14];
    const float* w2   = (const float*)d_in[15];
    const float* b2   = (const float*)d_in[16];

    float* X = (float*)d_out;

    __half *normed, *q, *k, *v, *attn, *ffh;
    __half *wq16, *wk16, *wv16, *wo16, *w116, *w216;
    cudaGetSymbolAddress((void**)&normed, g_normed);
    cudaGetSymbolAddress((void**)&q,      g_q);
    cudaGetSymbolAddress((void**)&k,      g_k);
    cudaGetSymbolAddress((void**)&v,      g_v);
    cudaGetSymbolAddress((void**)&attn,   g_attn);
    cudaGetSymbolAddress((void**)&ffh,    g_ffh);
    cudaGetSymbolAddress((void**)&wq16,   g_wq16);
    cudaGetSymbolAddress((void**)&wk16,   g_wk16);
    cudaGetSymbolAddress((void**)&wv16,   g_wv16);
    cudaGetSymbolAddress((void**)&wo16,   g_wo16);
    cudaGetSymbolAddress((void**)&w116,   g_w116);
    cudaGetSymbolAddress((void**)&w216,   g_w216);

    cudaFuncSetAttribute(attn_kernel,
                         cudaFuncAttributeMaxDynamicSharedMemorySize, ATTN_SMEM_BYTES);
    cudaFuncSetAttribute(gemm16_kernel<0>,
                         cudaFuncAttributeMaxDynamicSharedMemorySize, GEMM_SMEM_BYTES);
    cudaFuncSetAttribute(gemm16_kernel<1>,
                         cudaFuncAttributeMaxDynamicSharedMemorySize, GEMM_SMEM_BYTES);
    cudaFuncSetAttribute(gemm16_kernel<2>,
                         cudaFuncAttributeMaxDynamicSharedMemorySize, GEMM_SMEM_BYTES);
    cudaFuncSetAttribute(qkv16_kernel,
                         cudaFuncAttributeMaxDynamicSharedMemorySize, GEMM_SMEM_BYTES);

    cudaMemcpyAsync(X, x, (size_t)NTOK * D_MODEL * sizeof(float),
                    cudaMemcpyDeviceToDevice);

    cvt_all_kernel<<<(TOT4 + 255) / 256, 256>>>(wq, wk, wv, wo, w1, w2,
                                                wq16, wk16, wv16, wo16, w116, w216);

    const float qscale = 0.17677669529663687f * 1.4426950408889634f;

    const dim3 gemm_dd(D_MODEL / 64, NTOK / 64);
    const dim3 gemm_df(D_FF / 64,    NTOK / 64);
    const dim3 qkv_grid(D_MODEL / 64, NTOK / 64, 3);
    const dim3 attn_grid(SEQ / 128, N_HEADS, BATCH);

    for (int ly = 0; ly < N_LAYERS; ly++) {
        const int wdd = ly * D_MODEL * D_MODEL;
        const int wdf = ly * D_MODEL * D_FF;

        ln_kernel<<<NTOK / 8, 256>>>(X, ln1s + ly * D_MODEL, ln1b + ly * D_MODEL, normed);

        qkv16_kernel<<<qkv_grid, 128, GEMM_SMEM_BYTES>>>(
            normed, wq16 + wdd, wk16 + wdd, wv16 + wdd,
            bq + ly * D_MODEL, bk + ly * D_MODEL, bv + ly * D_MODEL,
            q, k, v, qscale);

        attn_kernel<<<attn_grid, 128, ATTN_SMEM_BYTES>>>(q, k, v, attn);

        gemm16_kernel<2><<<gemm_dd, 128, GEMM_SMEM_BYTES>>>(
            attn, wo16 + wdd, bo + ly * D_MODEL, (void*)X, D_MODEL, D_MODEL, 1.0f);

        ln_kernel<<<NTOK / 8, 256>>>(X, ln2s + ly * D_MODEL, ln2b + ly * D_MODEL, normed);

        gemm16_kernel<1><<<gemm_df, 128, GEMM_SMEM_BYTES>>>(
            normed, w116 + wdf, b1 + ly * D_FF, (void*)ffh, D_MODEL, D_FF, 1.0f);

        gemm16_kernel<2><<<gemm_dd, 128, GEMM_SMEM_BYTES>>>(
            ffh, w216 + wdf, b2 + ly * D_MODEL, (void*)X, D_FF, D_MODEL, 1.0f);
    }
}